// round 7
// baseline (speedup 1.0000x reference)
#include <cuda_runtime.h>
#include <math.h>

#define NN   4096
#define SEQ  41
#define VEC  15
#define TT   8
#define EMBD 32
#define LDIM 256
#define REDD 64
#define BN_EPS 1e-5f
#define FLATD (TT*VEC)   // 120

// ------------------------- device scratch ------------------------------------
__device__ float  g_h[NN*EMBD];
__device__ double g_bns[EMBD], g_bnq[EMBD];
__device__ float  g_scale[EMBD], g_shift[EMBD];
__device__ float  g_emb[NN*EMBD];
__device__ float  g_sqn[NN];
__device__ double g_dsum;
__device__ float  g_avg, g_mn, g_invrange;
__device__ unsigned g_minbits, g_maxbits;
__device__ float  g_pos[NN*REDD], g_neg[NN*REDD];
__device__ float  g_psqn[NN], g_nsqn[NN];
__device__ double g_psim, g_nsim;

// ------------------------- helpers -------------------------------------------
__device__ __forceinline__ unsigned f2tf32(float x) {
    unsigned u; asm("cvt.rna.tf32.f32 %0, %1;" : "=r"(u) : "f"(x)); return u;
}
__device__ __forceinline__ float tanha(float x) {
    float y; asm("tanh.approx.f32 %0, %1;" : "=f"(y) : "f"(x)); return y;
}
__device__ __forceinline__ float sqrta(float x) {
    float y; asm("sqrt.approx.f32 %0, %1;" : "=f"(y) : "f"(x)); return y;
}
__device__ __forceinline__ void mma_tf32(float c[4],
    unsigned a0, unsigned a1, unsigned a2, unsigned a3,
    unsigned b0, unsigned b1)
{
    asm("mma.sync.aligned.m16n8k8.row.col.f32.tf32.tf32.f32 "
        "{%0,%1,%2,%3}, {%4,%5,%6,%7}, {%8,%9}, {%0,%1,%2,%3};"
        : "+f"(c[0]), "+f"(c[1]), "+f"(c[2]), "+f"(c[3])
        : "r"(a0), "r"(a1), "r"(a2), "r"(a3), "r"(b0), "r"(b1));
}

// ------------------------- reset ---------------------------------------------
__global__ void k_reset() {
    g_dsum = 0.0; g_psim = 0.0; g_nsim = 0.0;
    g_minbits = 0x7f800000u;
    g_maxbits = 0u;
    for (int i = 0; i < EMBD; i++) { g_bns[i] = 0.0; g_bnq[i] = 0.0; }
}

// ---------------- interp gather + flat@W1 + tanh -> g_h ----------------------
__global__ void k_interp(const float* __restrict__ A, const int* __restrict__ C,
                         const float* __restrict__ W1, const float* __restrict__ b1)
{
    __shared__ float flat[8][128];
    int warp = threadIdx.x >> 5, lane = threadIdx.x & 31;
    int n = blockIdx.x * 8 + warp;
    int st = C[2*n], en = C[2*n+1];
    int len = en - st + 1;
    float scale = (float)len / (float)TT;
    const float* Ar = A + (size_t)n * SEQ * VEC;
    for (int k = lane; k < FLATD; k += 32) {
        int j = k / VEC, v = k - j * VEC;
        float src = fmaxf(scale * ((float)j + 0.5f) - 0.5f, 0.0f);
        int i0 = min((int)floorf(src), len - 1);
        int i1 = min(i0 + 1, len - 1);
        float w = src - (float)i0;
        float g0 = Ar[(st + i0) * VEC + v];
        float g1 = Ar[(st + i1) * VEC + v];
        flat[warp][k] = (1.0f - w) * g0 + w * g1;
    }
    __syncwarp();
    int o = lane;
    float acc = b1[o];
    #pragma unroll 8
    for (int k = 0; k < FLATD; k++)
        acc = fmaf(flat[warp][k], W1[k * EMBD + o], acc);
    g_h[n * EMBD + o] = tanhf(acc);
}

// ---------------- batchnorm stats (parallel, double atomics) -----------------
__global__ void k_bnstats()
{
    __shared__ float ss[8][32], sq2[8][32];
    int col = threadIdx.x & 31, seg = threadIdx.x >> 5;
    int r0 = blockIdx.x * 8 + seg;
    float s = 0.f, q = 0.f;
    for (int r = r0; r < NN; r += 512) {
        float h = g_h[r * EMBD + col];
        s += h; q = fmaf(h, h, q);
    }
    ss[seg][col] = s; sq2[seg][col] = q;
    __syncthreads();
    if (threadIdx.x < 32) {
        double S = 0.0, Q = 0.0;
        #pragma unroll
        for (int g = 0; g < 8; g++) { S += (double)ss[g][col]; Q += (double)sq2[g][col]; }
        atomicAdd(&g_bns[col], S);
        atomicAdd(&g_bnq[col], Q);
    }
}
__global__ void k_bnfin(const float* __restrict__ gamma, const float* __restrict__ beta)
{
    int col = threadIdx.x;
    float mu  = (float)(g_bns[col] / (double)NN);
    float var = (float)(g_bnq[col] / (double)NN) - mu * mu;
    float sc  = gamma[col] * rsqrtf(var + BN_EPS);
    g_scale[col] = sc;
    g_shift[col] = beta[col] - sc * mu;
}

// ---------------- emb + squared norms (warp per row) -------------------------
__global__ void k_emb()
{
    int warp = threadIdx.x >> 5, lane = threadIdx.x & 31;
    int n = blockIdx.x * 8 + warp;
    float e = g_scale[lane] * g_h[n * EMBD + lane] + g_shift[lane];
    g_emb[n * EMBD + lane] = e;
    float s = e * e;
    #pragma unroll
    for (int o = 16; o > 0; o >>= 1) s += __shfl_xor_sync(0xffffffffu, s, o);
    if (lane == 0) g_sqn[n] = s;
}

// ========== k_fused: proj1 + proj2 + all means, 2 n's (82 rows->96) per CTA ==
// 512 threads, 16 warps. Stage1 warp grid 2(M)x8(N): 3 mt x 3 nt per warp.
#define OFF_A   0
#define OFF_B   3456
#define OFF_HP  9856
#define OFF_HQ  16384
#define OFF_WPS 22912
#define OFF_WNS 23008
#define OFF_BSH 23104
#define OFF_FF  23296
#define OFF_PS  23424
#define FUSED_SMEM_BYTES (23552 * 4)

__global__ void __launch_bounds__(512, 1) k_fused(
    const float* __restrict__ L, const int* __restrict__ C,
    const float* __restrict__ Pw, const float* __restrict__ Nw,
    const float* __restrict__ Wp1, const float* __restrict__ bp1,
    const float* __restrict__ Wq1, const float* __restrict__ bq1,
    const float* __restrict__ Wa,  const float* __restrict__ ba,
    const float* __restrict__ Wp2, const float* __restrict__ bp2,
    const float* __restrict__ Wq2, const float* __restrict__ bq2,
    float* __restrict__ outFF)
{
    extern __shared__ float sm[];
    unsigned* Asm = (unsigned*)(sm + OFF_A);
    unsigned* Bsm = (unsigned*)(sm + OFF_B);
    unsigned* HPs = (unsigned*)(sm + OFF_HP);
    unsigned* HQs = (unsigned*)(sm + OFF_HQ);
    float* wps = sm + OFF_WPS;
    float* wns = sm + OFF_WNS;
    float* bsh = sm + OFF_BSH;
    float* FF  = sm + OFF_FF;
    float* PS  = sm + OFF_PS;

    int tid = threadIdx.x;
    int n0 = blockIdx.x * 2;
    size_t rb = (size_t)n0 * SEQ;

    if (tid < 128) { FF[tid] = 0.f; PS[tid] = 0.f; }
    if (tid < 96) {
        float vp = 0.f, vn = 0.f;
        if (tid < 82) {
            int nl = (tid >= 41);
            int nnx = n0 + nl, s = tid - nl * 41;
            int st = C[2*nnx], en = C[2*nnx+1];
            bool pm = (s >= st && s <= en);
            vp = pm ? Pw[nnx * SEQ + s] : 0.f;
            vn = pm ? 0.f : Nw[nnx * SEQ + s];
        }
        wps[tid] = vp; wns[tid] = vn;
    }
    for (int j = tid; j < 192; j += 512)
        bsh[j] = (j < 64) ? bp1[j] : (j < 128 ? bq1[j - 64] : ba[j - 128]);

    int warp = tid >> 5, lane = tid & 31, gid = lane >> 2, tig = lane & 3;
    int wm = warp >> 3, wn = warp & 7;   // 2(M) x 8(N)

    float acc[3][3][4];
    #pragma unroll
    for (int mt = 0; mt < 3; mt++)
        #pragma unroll
        for (int nt = 0; nt < 3; nt++)
            #pragma unroll
            for (int q = 0; q < 4; q++) acc[mt][nt][q] = 0.f;

    for (int k0 = 0; k0 < LDIM; k0 += 32) {
        __syncthreads();
        // A chunk: 96 rows x 32 cols = 768 float4 items
        for (int t = tid; t < 768; t += 512) {
            int rr = t >> 3, c4 = (t & 7) * 4;
            int gr = (rr < 82) ? rr : 81;
            float4 v = *(const float4*)&L[(rb + gr) * LDIM + k0 + c4];
            Asm[rr*36 + c4+0] = f2tf32(v.x);
            Asm[rr*36 + c4+1] = f2tf32(v.y);
            Asm[rr*36 + c4+2] = f2tf32(v.z);
            Asm[rr*36 + c4+3] = f2tf32(v.w);
        }
        for (int t = tid; t < 32 * 192; t += 512) {
            int k = t / 192, n = t - k * 192;
            int kk = k0 + k;
            float v = (n < 64) ? Wp1[kk * 64 + n]
                    : (n < 128 ? Wq1[kk * 64 + n - 64] : Wa[kk * 64 + n - 128]);
            Bsm[k * 200 + n] = f2tf32(v);
        }
        __syncthreads();
        #pragma unroll
        for (int ks = 0; ks < 4; ks++) {
            int kb = ks * 8;
            unsigned a[3][4];
            #pragma unroll
            for (int mt = 0; mt < 3; mt++) {
                int R = wm * 48 + mt * 16;
                a[mt][0] = Asm[(R+gid  )*36 + kb+tig];
                a[mt][1] = Asm[(R+gid+8)*36 + kb+tig];
                a[mt][2] = Asm[(R+gid  )*36 + kb+tig+4];
                a[mt][3] = Asm[(R+gid+8)*36 + kb+tig+4];
            }
            #pragma unroll
            for (int nt = 0; nt < 3; nt++) {
                int Cb = wn * 24 + nt * 8;
                unsigned b0 = Bsm[(kb+tig  )*200 + Cb+gid];
                unsigned b1 = Bsm[(kb+tig+4)*200 + Cb+gid];
                #pragma unroll
                for (int mt = 0; mt < 3; mt++)
                    mma_tf32(acc[mt][nt], a[mt][0], a[mt][1], a[mt][2], a[mt][3], b0, b1);
            }
        }
    }

    // stage1 epilogue: weights + bias + tanh -> HP/HQ smem (tf32) + FF sums
    #pragma unroll
    for (int mt = 0; mt < 3; mt++) {
        #pragma unroll
        for (int half = 0; half < 2; half++) {
            int r = wm * 48 + mt * 16 + gid + half * 8;
            bool valid = (r < 82);
            int nl = (r >= 41) ? 1 : 0;
            float wp = wps[r], wq = wns[r];
            #pragma unroll
            for (int nt = 0; nt < 3; nt++) {
                int j0 = wn * 24 + nt * 8 + tig * 2;
                int grp = j0 >> 6, jj = j0 & 63;
                float w = (grp == 0) ? wp : (grp == 1 ? wq : wp + wq);
                float v0 = tanha(fmaf(w, acc[mt][nt][half*2+0], bsh[j0]));
                float v1 = tanha(fmaf(w, acc[mt][nt][half*2+1], bsh[j0+1]));
                if (grp == 0)      { HPs[r*68+jj] = f2tf32(v0); HPs[r*68+jj+1] = f2tf32(v1); }
                else if (grp == 1) { HQs[r*68+jj] = f2tf32(v0); HQs[r*68+jj+1] = f2tf32(v1); }
                else if (valid) {
                    atomicAdd(&FF[nl*64 + jj],     v0);
                    atomicAdd(&FF[nl*64 + jj + 1], v1);
                }
            }
        }
    }
    __syncthreads();
    if (tid < 128) {
        int nl = tid >> 6, c = tid & 63;
        outFF[(size_t)(n0 + nl) * 64 + c] = FF[tid] * (1.0f / 41.0f);
    }

    // ---- stage 2: (96x64)@(64x64), per p in {pos,neg}; warp grid 2x8 -------
    for (int p = 0; p < 2; p++) {
        const float* W2 = p ? Wq2 : Wp2;
        const float* b2 = p ? bq2 : bp2;
        const unsigned* H = p ? HQs : HPs;
        float* outv = p ? g_neg : g_pos;
        __syncthreads();
        for (int t = tid; t < 4096; t += 512) {
            int k = t >> 6, n = t & 63;
            Bsm[k * 72 + n] = f2tf32(W2[t]);
        }
        if (tid < 64) bsh[tid] = b2[tid];
        __syncthreads();

        float acc2[3][4];
        #pragma unroll
        for (int mt = 0; mt < 3; mt++)
            #pragma unroll
            for (int q = 0; q < 4; q++) acc2[mt][q] = 0.f;

        int Cb = wn * 8;
        #pragma unroll
        for (int ks = 0; ks < 8; ks++) {
            int kb = ks * 8;
            unsigned b0 = Bsm[(kb+tig  )*72 + Cb+gid];
            unsigned b1 = Bsm[(kb+tig+4)*72 + Cb+gid];
            #pragma unroll
            for (int mt = 0; mt < 3; mt++) {
                int R = wm * 48 + mt * 16;
                unsigned a0 = H[(R+gid  )*68 + kb+tig];
                unsigned a1 = H[(R+gid+8)*68 + kb+tig];
                unsigned a2 = H[(R+gid  )*68 + kb+tig+4];
                unsigned a3 = H[(R+gid+8)*68 + kb+tig+4];
                mma_tf32(acc2[mt], a0, a1, a2, a3, b0, b1);
            }
        }
        #pragma unroll
        for (int mt = 0; mt < 3; mt++)
            #pragma unroll
            for (int half = 0; half < 2; half++) {
                int r = wm * 48 + mt * 16 + gid + half * 8;
                bool valid = (r < 82);
                int nl = (r >= 41) ? 1 : 0;
                int j = Cb + tig * 2;
                float v0 = tanha(acc2[mt][half*2+0] + bsh[j]);
                float v1 = tanha(acc2[mt][half*2+1] + bsh[j+1]);
                if (valid) {
                    atomicAdd(&PS[nl*64 + j],     v0);
                    atomicAdd(&PS[nl*64 + j + 1], v1);
                }
            }
        __syncthreads();
        if (tid < 128) {
            int nl = tid >> 6, c = tid & 63;
            outv[(size_t)(n0 + nl) * 64 + c] = PS[tid] * (1.0f / 41.0f);
            PS[tid] = 0.f;
        }
    }
}

// ---------------- D0: scalar fp32 gram (precision!) + sum + RAW minmax -------
// outD base is 4-byte aligned only -> scalar stores.
__global__ void __launch_bounds__(256) k_d0(const float* __restrict__ sigma,
                                            float* __restrict__ outD)
{
    __shared__ float Ei[64][33], Ej[64][33];
    __shared__ float sred[256];
    __shared__ unsigned smn[256], smx[256];
    int i0 = blockIdx.y * 64, j0 = blockIdx.x * 64;
    int tid = threadIdx.x;
    for (int t = tid; t < 64 * 32; t += 256) {
        int r = t >> 5, c = t & 31;
        Ei[r][c] = g_emb[(i0 + r) * EMBD + c];
        Ej[r][c] = g_emb[(j0 + r) * EMBD + c];
    }
    __syncthreads();
    float inv = 1.0f / (2.0f * sigma[0] * sigma[0]);
    int tx = tid & 15, ty = tid >> 4;
    float acc[4][4];
    #pragma unroll
    for (int a = 0; a < 4; a++)
        #pragma unroll
        for (int b = 0; b < 4; b++) acc[a][b] = 0.0f;
    #pragma unroll 4
    for (int k = 0; k < 32; k++) {
        float av[4], bv[4];
        #pragma unroll
        for (int a = 0; a < 4; a++) av[a] = Ei[ty * 4 + a][k];
        #pragma unroll
        for (int b = 0; b < 4; b++) bv[b] = Ej[tx * 4 + b][k];
        #pragma unroll
        for (int a = 0; a < 4; a++)
            #pragma unroll
            for (int b = 0; b < 4; b++) acc[a][b] = fmaf(av[a], bv[b], acc[a][b]);
    }
    float lsum = 0.0f;
    unsigned mn = 0x7f800000u, mx = 0u;
    #pragma unroll
    for (int a = 0; a < 4; a++) {
        int i = i0 + ty * 4 + a;
        float si = g_sqn[i];
        #pragma unroll
        for (int b = 0; b < 4; b++) {
            int j = j0 + tx * 4 + b;
            float sqv = si + g_sqn[j] - 2.0f * acc[a][b];
            sqv = fmaxf(sqv, 0.0f);
            float d = (sqv > 0.0f) ? sqrta(sqv) : 0.0f;
            float e = __expf(-d * inv);
            if (i != j) {
                lsum += e;
                unsigned bb = __float_as_uint(e);
                mn = min(mn, bb); mx = max(mx, bb);
            }
            outD[(size_t)i * NN + (size_t)j] = e;
        }
    }
    sred[tid] = lsum; smn[tid] = mn; smx[tid] = mx;
    __syncthreads();
    for (int s2 = 128; s2 > 0; s2 >>= 1) {
        if (tid < s2) {
            sred[tid] += sred[tid + s2];
            smn[tid] = min(smn[tid], smn[tid + s2]);
            smx[tid] = max(smx[tid], smx[tid + s2]);
        }
        __syncthreads();
    }
    if (tid == 0) {
        atomicAdd(&g_dsum, (double)sred[0]);
        atomicMin(&g_minbits, smn[0]);
        atomicMax(&g_maxbits, smx[0]);
    }
}

// avg + derive thresholded min/max from raw minmax
__global__ void k_avg() {
    float avg = (float)(g_dsum / ((double)NN * (double)(NN - 1)));
    g_avg = avg;
    float mnr = __uint_as_float(g_minbits);
    float mxr = __uint_as_float(g_maxbits);
    float mn = (mnr < avg) ? 0.0f : mnr;
    float mx = mxr;
    if (mx == mn) mx = mn + 1.0f;
    g_mn = mn; g_invrange = 1.0f / (mx - mn);
}

// ---------------- final D normalize ------------------------------------------
__global__ void k_dfinal(float* __restrict__ outD)
{
    float avg = g_avg, mn = g_mn, inv = g_invrange;
    long long total = (long long)NN * NN;
    for (long long idx = (long long)blockIdx.x * blockDim.x + threadIdx.x; idx < total;
         idx += (long long)gridDim.x * blockDim.x) {
        int i = (int)(idx >> 12), j = (int)(idx & (NN - 1));
        float d = outD[idx];
        float t = (d < avg) ? 0.0f : d;
        float v = (t - mn) * inv;
        if (i == j) v = 1.0f;
        outD[idx] = v;
    }
}

// ---------------- squared norms of pos/neg vectors ---------------------------
__global__ void k_vecsqn()
{
    int n = blockIdx.x * blockDim.x + threadIdx.x;
    if (n >= NN) return;
    float a = 0.0f, b = 0.0f;
    #pragma unroll 8
    for (int o = 0; o < REDD; o++) {
        float p = g_pos[n * REDD + o]; a = fmaf(p, p, a);
        float q = g_neg[n * REDD + o]; b = fmaf(q, q, b);
    }
    g_psqn[n] = a; g_nsqn[n] = b;
}

// ========== k_simmma: 128x128 tiles of exp(-cdist) sums via tf32 mma ========
#define SIM_SMEM_BYTES (2 * 128 * 68 * 4)
__global__ void __launch_bounds__(256) k_simmma()
{
    extern __shared__ unsigned simsm[];
    unsigned* Xsm = simsm;
    unsigned* Ysm = simsm + 128 * 68;
    __shared__ float xq[128], yq[128];
    __shared__ float sred[256];
    int tid = threadIdx.x;
    int zi = blockIdx.z;
    int i0 = blockIdx.y * 128, j0 = blockIdx.x * 128;
    const float* Ys  = zi ? g_neg  : g_pos;
    const float* Ysq = zi ? g_nsqn : g_psqn;
    for (int t = tid; t < 128 * 16; t += 256) {
        int r = t >> 4, c4 = (t & 15) * 4;
        float4 v = *(const float4*)&g_pos[(size_t)(i0 + r) * REDD + c4];
        Xsm[r*68+c4+0] = f2tf32(v.x); Xsm[r*68+c4+1] = f2tf32(v.y);
        Xsm[r*68+c4+2] = f2tf32(v.z); Xsm[r*68+c4+3] = f2tf32(v.w);
        float4 w = *(const float4*)&Ys[(size_t)(j0 + r) * REDD + c4];
        Ysm[r*68+c4+0] = f2tf32(w.x); Ysm[r*68+c4+1] = f2tf32(w.y);
        Ysm[r*68+c4+2] = f2tf32(w.z); Ysm[r*68+c4+3] = f2tf32(w.w);
    }
    if (tid < 128) { xq[tid] = g_psqn[i0 + tid]; yq[tid] = Ysq[j0 + tid]; }
    __syncthreads();

    int warp = tid >> 5, lane = tid & 31, gid = lane >> 2, tig = lane & 3;
    int wm = warp >> 2, wn = warp & 3;
    float acc[4][4][4];
    #pragma unroll
    for (int mt = 0; mt < 4; mt++)
        #pragma unroll
        for (int nt = 0; nt < 4; nt++)
            #pragma unroll
            for (int q = 0; q < 4; q++) acc[mt][nt][q] = 0.f;

    #pragma unroll
    for (int ks = 0; ks < 8; ks++) {
        int kb = ks * 8;
        unsigned a[4][4];
        #pragma unroll
        for (int mt = 0; mt < 4; mt++) {
            int R = wm * 64 + mt * 16;
            a[mt][0] = Xsm[(R+gid  )*68 + kb+tig];
            a[mt][1] = Xsm[(R+gid+8)*68 + kb+tig];
            a[mt][2] = Xsm[(R+gid  )*68 + kb+tig+4];
            a[mt][3] = Xsm[(R+gid+8)*68 + kb+tig+4];
        }
        #pragma unroll
        for (int nt = 0; nt < 4; nt++) {
            int Cb = wn * 32 + nt * 8;
            unsigned b0 = Ysm[(Cb+gid)*68 + kb+tig];
            unsigned b1 = Ysm[(Cb+gid)*68 + kb+tig+4];
            #pragma unroll
            for (int mt = 0; mt < 4; mt++)
                mma_tf32(acc[mt][nt], a[mt][0], a[mt][1], a[mt][2], a[mt][3], b0, b1);
        }
    }
    float lsum = 0.f;
    #pragma unroll
    for (int mt = 0; mt < 4; mt++)
        #pragma unroll
        for (int nt = 0; nt < 4; nt++)
            #pragma unroll
            for (int q = 0; q < 4; q++) {
                int il = wm*64 + mt*16 + gid + ((q >> 1) << 3);
                int jl = wn*32 + nt*8  + tig*2 + (q & 1);
                float sq = xq[il] + yq[jl] - 2.0f * acc[mt][nt][q];
                sq = fmaxf(sq, 0.f);
                float d = (sq > 0.f) ? sqrta(sq) : 0.f;
                lsum += __expf(-d);
            }
    sred[tid] = lsum;
    __syncthreads();
    for (int s2 = 128; s2 > 0; s2 >>= 1) {
        if (tid < s2) sred[tid] += sred[tid + s2];
        __syncthreads();
    }
    if (tid == 0) atomicAdd(zi ? &g_nsim : &g_psim, (double)sred[0]);
}

__global__ void k_loss(float* __restrict__ o)
{
    o[0] = (float)(log(g_nsim) - log(g_psim));
}

// ----------------------------- launcher --------------------------------------
extern "C" void kernel_launch(void* const* d_in, const int* in_sizes, int n_in,
                              void* d_out, int out_size)
{
    const float* A     = (const float*)d_in[0];
    const int*   C     = (const int*)  d_in[1];
    const float* L     = (const float*)d_in[2];
    const float* W1    = (const float*)d_in[3];
    const float* b1    = (const float*)d_in[4];
    const float* gamma = (const float*)d_in[5];
    const float* beta  = (const float*)d_in[6];
    const float* sigma = (const float*)d_in[7];
    const float* Pw    = (const float*)d_in[8];
    const float* Nw    = (const float*)d_in[9];
    const float* Wp1   = (const float*)d_in[10];
    const float* bp1   = (const float*)d_in[11];
    const float* Wp2   = (const float*)d_in[12];
    const float* bp2   = (const float*)d_in[13];
    const float* Wq1   = (const float*)d_in[14];
    const float* bq1   = (const float*)d_in[15];
    const float* Wq2   = (const float*)d_in[16];
    const float* bq2   = (const float*)d_in[17];
    const float* Wa    = (const float*)d_in[18];
    const float* ba    = (const float*)d_in[19];

    float* out   = (float*)d_out;
    float* outFF = out;                 // [4096*64]
    float* outL  = out + NN * REDD;     // [1]
    float* outD  = out + NN * REDD + 1; // [4096*4096], only 4B-aligned

    cudaFuncSetAttribute(k_fused, cudaFuncAttributeMaxDynamicSharedMemorySize, FUSED_SMEM_BYTES);
    cudaFuncSetAttribute(k_simmma, cudaFuncAttributeMaxDynamicSharedMemorySize, SIM_SMEM_BYTES);

    // NOTE: k_fused is the 6th launch so ncu (-s 5 -c 1) profiles it.
    k_reset<<<1, 1>>>();
    k_interp<<<NN / 8, 256>>>(A, C, W1, b1);
    k_bnstats<<<64, 256>>>();
    k_bnfin<<<1, 32>>>(gamma, beta);
    k_emb<<<NN / 8, 256>>>();
    k_fused<<<NN / 2, 512, FUSED_SMEM_BYTES>>>(L, C, Pw, Nw,
                                               Wp1, bp1, Wq1, bq1, Wa, ba,
                                               Wp2, bp2, Wq2, bq2, outFF);
    k_d0<<<dim3(64, 64), 256>>>(sigma, outD);
    k_avg<<<1, 1>>>();
    k_dfinal<<<4096, 256>>>(outD);
    k_vecsqn<<<16, 256>>>();
    k_simmma<<<dim3(32, 32, 2), 256, SIM_SMEM_BYTES>>>();
    k_loss<<<1, 1>>>(outL);
}

// round 9
// speedup vs baseline: 1.0091x; 1.0091x over previous
#include <cuda_runtime.h>
#include <math.h>

#define NN   4096
#define SEQ  41
#define VEC  15
#define TT   8
#define EMBD 32
#define LDIM 256
#define REDD 64
#define BN_EPS 1e-5f
#define FLATD (TT*VEC)   // 120

// ------------------------- device scratch ------------------------------------
__device__ float  g_h[NN*EMBD];
__device__ double g_bns[EMBD], g_bnq[EMBD];
__device__ float  g_scale[EMBD], g_shift[EMBD];
__device__ float  g_emb[NN*EMBD];
__device__ float  g_sqn[NN];
__device__ double g_dsum;
__device__ float  g_avg, g_mn, g_invrange;
__device__ unsigned g_minbits, g_maxbits;
__device__ float  g_pos[NN*REDD], g_neg[NN*REDD];
__device__ float  g_psqn[NN], g_nsqn[NN];
__device__ double g_psim, g_nsim;

// ------------------------- helpers -------------------------------------------
__device__ __forceinline__ unsigned f2tf32(float x) {
    unsigned u; asm("cvt.rna.tf32.f32 %0, %1;" : "=r"(u) : "f"(x)); return u;
}
__device__ __forceinline__ float tanha(float x) {
    float y; asm("tanh.approx.f32 %0, %1;" : "=f"(y) : "f"(x)); return y;
}
__device__ __forceinline__ float sqrta(float x) {
    float y; asm("sqrt.approx.f32 %0, %1;" : "=f"(y) : "f"(x)); return y;
}
__device__ __forceinline__ void mma_tf32(float c[4],
    unsigned a0, unsigned a1, unsigned a2, unsigned a3,
    unsigned b0, unsigned b1)
{
    asm("mma.sync.aligned.m16n8k8.row.col.f32.tf32.tf32.f32 "
        "{%0,%1,%2,%3}, {%4,%5,%6,%7}, {%8,%9}, {%0,%1,%2,%3};"
        : "+f"(c[0]), "+f"(c[1]), "+f"(c[2]), "+f"(c[3])
        : "r"(a0), "r"(a1), "r"(a2), "r"(a3), "r"(b0), "r"(b1));
}

// ------------------------- reset ---------------------------------------------
__global__ void k_reset() {
    g_dsum = 0.0; g_psim = 0.0; g_nsim = 0.0;
    g_minbits = 0x7f800000u;
    g_maxbits = 0u;
    for (int i = 0; i < EMBD; i++) { g_bns[i] = 0.0; g_bnq[i] = 0.0; }
}

// ---------------- interp gather + flat@W1 + tanh -> g_h ----------------------
__global__ void k_interp(const float* __restrict__ A, const int* __restrict__ C,
                         const float* __restrict__ W1, const float* __restrict__ b1)
{
    __shared__ float flat[8][128];
    __shared__ float w1s[FLATD * EMBD];   // 15.4 KB
    int tid = threadIdx.x;
    for (int t = tid; t < FLATD * EMBD / 4; t += 256)
        *(float4*)&w1s[t * 4] = *(const float4*)&W1[t * 4];
    int warp = tid >> 5, lane = tid & 31;
    int n = blockIdx.x * 8 + warp;
    int st = C[2*n], en = C[2*n+1];
    int len = en - st + 1;
    float scale = (float)len / (float)TT;
    const float* Ar = A + (size_t)n * SEQ * VEC;
    for (int k = lane; k < FLATD; k += 32) {
        int j = k / VEC, v = k - j * VEC;
        float src = fmaxf(scale * ((float)j + 0.5f) - 0.5f, 0.0f);
        int i0 = min((int)floorf(src), len - 1);
        int i1 = min(i0 + 1, len - 1);
        float w = src - (float)i0;
        float g0 = Ar[(st + i0) * VEC + v];
        float g1 = Ar[(st + i1) * VEC + v];
        flat[warp][k] = (1.0f - w) * g0 + w * g1;
    }
    __syncthreads();
    int o = lane;
    float acc = b1[o];
    #pragma unroll 8
    for (int k = 0; k < FLATD; k++)
        acc = fmaf(flat[warp][k], w1s[k * EMBD + o], acc);
    g_h[n * EMBD + o] = tanhf(acc);
}

// ---------------- batchnorm stats (parallel, double atomics) -----------------
__global__ void k_bnstats()
{
    __shared__ float ss[8][32], sq2[8][32];
    int col = threadIdx.x & 31, seg = threadIdx.x >> 5;
    int r0 = blockIdx.x * 8 + seg;
    float s = 0.f, q = 0.f;
    for (int r = r0; r < NN; r += 512) {
        float h = g_h[r * EMBD + col];
        s += h; q = fmaf(h, h, q);
    }
    ss[seg][col] = s; sq2[seg][col] = q;
    __syncthreads();
    if (threadIdx.x < 32) {
        double S = 0.0, Q = 0.0;
        #pragma unroll
        for (int g = 0; g < 8; g++) { S += (double)ss[g][col]; Q += (double)sq2[g][col]; }
        atomicAdd(&g_bns[col], S);
        atomicAdd(&g_bnq[col], Q);
    }
}
__global__ void k_bnfin(const float* __restrict__ gamma, const float* __restrict__ beta)
{
    int col = threadIdx.x;
    float mu  = (float)(g_bns[col] / (double)NN);
    float var = (float)(g_bnq[col] / (double)NN) - mu * mu;
    float sc  = gamma[col] * rsqrtf(var + BN_EPS);
    g_scale[col] = sc;
    g_shift[col] = beta[col] - sc * mu;
}

// ---------------- emb + squared norms (warp per row) -------------------------
__global__ void k_emb()
{
    int warp = threadIdx.x >> 5, lane = threadIdx.x & 31;
    int n = blockIdx.x * 8 + warp;
    float e = g_scale[lane] * g_h[n * EMBD + lane] + g_shift[lane];
    g_emb[n * EMBD + lane] = e;
    float s = e * e;
    #pragma unroll
    for (int o = 16; o > 0; o >>= 1) s += __shfl_xor_sync(0xffffffffu, s, o);
    if (lane == 0) g_sqn[n] = s;
}

// ========== k_fused: proj1 + proj2 + all means, 2 n's (82 rows->96) per CTA ==
// 256 threads, 8 warps. Stage1 warp grid 2(M)x4(N): 3 mt x 6 nt per warp.
#define OFF_A   0
#define OFF_B   3456
#define OFF_HP  9856
#define OFF_HQ  16384
#define OFF_WPS 22912
#define OFF_WNS 23008
#define OFF_BSH 23104
#define OFF_FF  23296
#define OFF_PS  23424
#define FUSED_SMEM_BYTES (23552 * 4)

__global__ void __launch_bounds__(256) k_fused(
    const float* __restrict__ L, const int* __restrict__ C,
    const float* __restrict__ Pw, const float* __restrict__ Nw,
    const float* __restrict__ Wp1, const float* __restrict__ bp1,
    const float* __restrict__ Wq1, const float* __restrict__ bq1,
    const float* __restrict__ Wa,  const float* __restrict__ ba,
    const float* __restrict__ Wp2, const float* __restrict__ bp2,
    const float* __restrict__ Wq2, const float* __restrict__ bq2,
    float* __restrict__ outFF)
{
    extern __shared__ float sm[];
    unsigned* Asm = (unsigned*)(sm + OFF_A);
    unsigned* Bsm = (unsigned*)(sm + OFF_B);
    unsigned* HPs = (unsigned*)(sm + OFF_HP);
    unsigned* HQs = (unsigned*)(sm + OFF_HQ);
    float* wps = sm + OFF_WPS;
    float* wns = sm + OFF_WNS;
    float* bsh = sm + OFF_BSH;
    float* FF  = sm + OFF_FF;
    float* PS  = sm + OFF_PS;

    int tid = threadIdx.x;
    int n0 = blockIdx.x * 2;
    size_t rb = (size_t)n0 * SEQ;

    if (tid < 128) { FF[tid] = 0.f; PS[tid] = 0.f; }
    if (tid < 96) {
        float vp = 0.f, vn = 0.f;
        if (tid < 82) {
            int nl = (tid >= 41);
            int nnx = n0 + nl, s = tid - nl * 41;
            int st = C[2*nnx], en = C[2*nnx+1];
            bool pm = (s >= st && s <= en);
            vp = pm ? Pw[nnx * SEQ + s] : 0.f;
            vn = pm ? 0.f : Nw[nnx * SEQ + s];
        }
        wps[tid] = vp; wns[tid] = vn;
    }
    for (int j = tid; j < 192; j += 256)
        bsh[j] = (j < 64) ? bp1[j] : (j < 128 ? bq1[j - 64] : ba[j - 128]);

    int warp = tid >> 5, lane = tid & 31, gid = lane >> 2, tig = lane & 3;
    int wm = warp >> 2, wn = warp & 3;   // 2(M) x 4(N)

    float acc[3][6][4];
    #pragma unroll
    for (int mt = 0; mt < 3; mt++)
        #pragma unroll
        for (int nt = 0; nt < 6; nt++)
            #pragma unroll
            for (int q = 0; q < 4; q++) acc[mt][nt][q] = 0.f;

    for (int k0 = 0; k0 < LDIM; k0 += 32) {
        __syncthreads();
        {   // A chunk: 96 rows x 32 cols (pad rows clamp to row 81), float4
            int r0 = tid >> 3, c4 = (tid & 7) * 4;
            #pragma unroll
            for (int i = 0; i < 3; i++) {
                int rr = r0 + i * 32;
                int gr = (rr < 82) ? rr : 81;
                float4 v = *(const float4*)&L[(rb + gr) * LDIM + k0 + c4];
                Asm[rr*36 + c4+0] = f2tf32(v.x);
                Asm[rr*36 + c4+1] = f2tf32(v.y);
                Asm[rr*36 + c4+2] = f2tf32(v.z);
                Asm[rr*36 + c4+3] = f2tf32(v.w);
            }
        }
        // B chunk: 32 k x 192 n as float4 (48 quads/row); 1536 quads total
        for (int t = tid; t < 1536; t += 256) {
            int k = t / 48, q = t - k * 48;
            int n = q * 4;
            int kk = k0 + k;
            int grp = n >> 6, jj = n & 63;
            const float* src = (grp == 0) ? Wp1 : (grp == 1 ? Wq1 : Wa);
            float4 v = *(const float4*)&src[kk * 64 + jj];
            uint4 u;
            u.x = f2tf32(v.x); u.y = f2tf32(v.y);
            u.z = f2tf32(v.z); u.w = f2tf32(v.w);
            *(uint4*)&Bsm[k * 200 + n] = u;
        }
        __syncthreads();
        #pragma unroll
        for (int ks = 0; ks < 4; ks++) {
            int kb = ks * 8;
            unsigned a[3][4];
            #pragma unroll
            for (int mt = 0; mt < 3; mt++) {
                int R = wm * 48 + mt * 16;
                a[mt][0] = Asm[(R+gid  )*36 + kb+tig];
                a[mt][1] = Asm[(R+gid+8)*36 + kb+tig];
                a[mt][2] = Asm[(R+gid  )*36 + kb+tig+4];
                a[mt][3] = Asm[(R+gid+8)*36 + kb+tig+4];
            }
            #pragma unroll
            for (int nt = 0; nt < 6; nt++) {
                int Cb = wn * 48 + nt * 8;
                unsigned b0 = Bsm[(kb+tig  )*200 + Cb+gid];
                unsigned b1 = Bsm[(kb+tig+4)*200 + Cb+gid];
                #pragma unroll
                for (int mt = 0; mt < 3; mt++)
                    mma_tf32(acc[mt][nt], a[mt][0], a[mt][1], a[mt][2], a[mt][3], b0, b1);
            }
        }
    }

    // stage1 epilogue: weights + bias + tanh -> HP/HQ smem (tf32) + FF sums
    #pragma unroll
    for (int mt = 0; mt < 3; mt++) {
        #pragma unroll
        for (int half = 0; half < 2; half++) {
            int r = wm * 48 + mt * 16 + gid + half * 8;
            bool valid = (r < 82);
            int nl = (r >= 41) ? 1 : 0;
            float wp = wps[r], wq = wns[r];
            #pragma unroll
            for (int nt = 0; nt < 6; nt++) {
                int j0 = wn * 48 + nt * 8 + tig * 2;
                int grp = j0 >> 6, jj = j0 & 63;
                float w = (grp == 0) ? wp : (grp == 1 ? wq : wp + wq);
                float v0 = tanha(fmaf(w, acc[mt][nt][half*2+0], bsh[j0]));
                float v1 = tanha(fmaf(w, acc[mt][nt][half*2+1], bsh[j0+1]));
                if (grp == 0)      { HPs[r*68+jj] = f2tf32(v0); HPs[r*68+jj+1] = f2tf32(v1); }
                else if (grp == 1) { HQs[r*68+jj] = f2tf32(v0); HQs[r*68+jj+1] = f2tf32(v1); }
                else if (valid) {
                    atomicAdd(&FF[nl*64 + jj],     v0);
                    atomicAdd(&FF[nl*64 + jj + 1], v1);
                }
            }
        }
    }
    __syncthreads();
    if (tid < 128) {
        int nl = tid >> 6, c = tid & 63;
        outFF[(size_t)(n0 + nl) * 64 + c] = FF[tid] * (1.0f / 41.0f);
    }

    // ---- stage 2: (96x64)@(64x64), per p in {pos,neg}; warp grid 2x4 -------
    for (int p = 0; p < 2; p++) {
        const float* W2 = p ? Wq2 : Wp2;
        const float* b2 = p ? bq2 : bp2;
        const unsigned* H = p ? HQs : HPs;
        float* outv = p ? g_neg : g_pos;
        __syncthreads();
        for (int t = tid; t < 1024; t += 256) {      // 64x64 as float4
            int k = t >> 4, n = (t & 15) * 4;
            float4 v = *(const float4*)&W2[k * 64 + n];
            uint4 u;
            u.x = f2tf32(v.x); u.y = f2tf32(v.y);
            u.z = f2tf32(v.z); u.w = f2tf32(v.w);
            *(uint4*)&Bsm[k * 72 + n] = u;
        }
        if (tid < 64) bsh[tid] = b2[tid];
        __syncthreads();

        float acc2[3][2][4];
        #pragma unroll
        for (int mt = 0; mt < 3; mt++)
            #pragma unroll
            for (int nt = 0; nt < 2; nt++)
                #pragma unroll
                for (int q = 0; q < 4; q++) acc2[mt][nt][q] = 0.f;

        #pragma unroll
        for (int ks = 0; ks < 8; ks++) {
            int kb = ks * 8;
            unsigned a[3][4];
            #pragma unroll
            for (int mt = 0; mt < 3; mt++) {
                int R = wm * 48 + mt * 16;
                a[mt][0] = H[(R+gid  )*68 + kb+tig];
                a[mt][1] = H[(R+gid+8)*68 + kb+tig];
                a[mt][2] = H[(R+gid  )*68 + kb+tig+4];
                a[mt][3] = H[(R+gid+8)*68 + kb+tig+4];
            }
            #pragma unroll
            for (int nt = 0; nt < 2; nt++) {
                int Cb = wn * 16 + nt * 8;
                unsigned b0 = Bsm[(kb+tig  )*72 + Cb+gid];
                unsigned b1 = Bsm[(kb+tig+4)*72 + Cb+gid];
                #pragma unroll
                for (int mt = 0; mt < 3; mt++)
                    mma_tf32(acc2[mt][nt], a[mt][0], a[mt][1], a[mt][2], a[mt][3], b0, b1);
            }
        }
        #pragma unroll
        for (int mt = 0; mt < 3; mt++)
            #pragma unroll
            for (int half = 0; half < 2; half++) {
                int r = wm * 48 + mt * 16 + gid + half * 8;
                bool valid = (r < 82);
                int nl = (r >= 41) ? 1 : 0;
                #pragma unroll
                for (int nt = 0; nt < 2; nt++) {
                    int j = wn * 16 + nt * 8 + tig * 2;
                    float v0 = tanha(acc2[mt][nt][half*2+0] + bsh[j]);
                    float v1 = tanha(acc2[mt][nt][half*2+1] + bsh[j+1]);
                    if (valid) {
                        atomicAdd(&PS[nl*64 + j],     v0);
                        atomicAdd(&PS[nl*64 + j + 1], v1);
                    }
                }
            }
        __syncthreads();
        if (tid < 128) {
            int nl = tid >> 6, c = tid & 63;
            outv[(size_t)(n0 + nl) * 64 + c] = PS[tid] * (1.0f / 41.0f);
            PS[tid] = 0.f;
        }
    }
}

// ---------------- D0: scalar fp32 gram (precision!) + sum + RAW minmax -------
// outD base is 4-byte aligned only -> scalar stores.
__global__ void __launch_bounds__(256) k_d0(const float* __restrict__ sigma,
                                            float* __restrict__ outD)
{
    __shared__ float Ei[64][33], Ej[64][33];
    __shared__ float sred[256];
    __shared__ unsigned smn[256], smx[256];
    int i0 = blockIdx.y * 64, j0 = blockIdx.x * 64;
    int tid = threadIdx.x;
    for (int t = tid; t < 64 * 32; t += 256) {
        int r = t >> 5, c = t & 31;
        Ei[r][c] = g_emb[(i0 + r) * EMBD + c];
        Ej[r][c] = g_emb[(j0 + r) * EMBD + c];
    }
    __syncthreads();
    float inv = 1.0f / (2.0f * sigma[0] * sigma[0]);
    int tx = tid & 15, ty = tid >> 4;
    float acc[4][4];
    #pragma unroll
    for (int a = 0; a < 4; a++)
        #pragma unroll
        for (int b = 0; b < 4; b++) acc[a][b] = 0.0f;
    #pragma unroll 4
    for (int k = 0; k < 32; k++) {
        float av[4], bv[4];
        #pragma unroll
        for (int a = 0; a < 4; a++) av[a] = Ei[ty * 4 + a][k];
        #pragma unroll
        for (int b = 0; b < 4; b++) bv[b] = Ej[tx * 4 + b][k];
        #pragma unroll
        for (int a = 0; a < 4; a++)
            #pragma unroll
            for (int b = 0; b < 4; b++) acc[a][b] = fmaf(av[a], bv[b], acc[a][b]);
    }
    float lsum = 0.0f;
    unsigned mn = 0x7f800000u, mx = 0u;
    #pragma unroll
    for (int a = 0; a < 4; a++) {
        int i = i0 + ty * 4 + a;
        float si = g_sqn[i];
        #pragma unroll
        for (int b = 0; b < 4; b++) {
            int j = j0 + tx * 4 + b;
            float sqv = si + g_sqn[j] - 2.0f * acc[a][b];
            sqv = fmaxf(sqv, 0.0f);
            float d = (sqv > 0.0f) ? sqrta(sqv) : 0.0f;
            float e = __expf(-d * inv);
            if (i != j) {
                lsum += e;
                unsigned bb = __float_as_uint(e);
                mn = min(mn, bb); mx = max(mx, bb);
            }
            outD[(size_t)i * NN + (size_t)j] = e;
        }
    }
    sred[tid] = lsum; smn[tid] = mn; smx[tid] = mx;
    __syncthreads();
    for (int s2 = 128; s2 > 0; s2 >>= 1) {
        if (tid < s2) {
            sred[tid] += sred[tid + s2];
            smn[tid] = min(smn[tid], smn[tid + s2]);
            smx[tid] = max(smx[tid], smx[tid + s2]);
        }
        __syncthreads();
    }
    if (tid == 0) {
        atomicAdd(&g_dsum, (double)sred[0]);
        atomicMin(&g_minbits, smn[0]);
        atomicMax(&g_maxbits, smx[0]);
    }
}

// avg + derive thresholded min/max from raw minmax
__global__ void k_avg() {
    float avg = (float)(g_dsum / ((double)NN * (double)(NN - 1)));
    g_avg = avg;
    float mnr = __uint_as_float(g_minbits);
    float mxr = __uint_as_float(g_maxbits);
    float mn = (mnr < avg) ? 0.0f : mnr;
    float mx = mxr;
    if (mx == mn) mx = mn + 1.0f;
    g_mn = mn; g_invrange = 1.0f / (mx - mn);
}

// ---------------- final D normalize ------------------------------------------
__global__ void k_dfinal(float* __restrict__ outD)
{
    float avg = g_avg, mn = g_mn, inv = g_invrange;
    long long total = (long long)NN * NN;
    for (long long idx = (long long)blockIdx.x * blockDim.x + threadIdx.x; idx < total;
         idx += (long long)gridDim.x * blockDim.x) {
        int i = (int)(idx >> 12), j = (int)(idx & (NN - 1));
        float d = outD[idx];
        float t = (d < avg) ? 0.0f : d;
        float v = (t - mn) * inv;
        if (i == j) v = 1.0f;
        outD[idx] = v;
    }
}

// ---------------- squared norms of pos/neg vectors ---------------------------
__global__ void k_vecsqn()
{
    int n = blockIdx.x * blockDim.x + threadIdx.x;
    if (n >= NN) return;
    float a = 0.0f, b = 0.0f;
    #pragma unroll 8
    for (int o = 0; o < REDD; o++) {
        float p = g_pos[n * REDD + o]; a = fmaf(p, p, a);
        float q = g_neg[n * REDD + o]; b = fmaf(q, q, b);
    }
    g_psqn[n] = a; g_nsqn[n] = b;
}

// ========== k_simmma: 128x128 tiles of exp(-cdist) sums via tf32 mma ========
#define SIM_SMEM_BYTES (2 * 128 * 68 * 4)
__global__ void __launch_bounds__(256) k_simmma()
{
    extern __shared__ unsigned simsm[];
    unsigned* Xsm = simsm;
    unsigned* Ysm = simsm + 128 * 68;
    __shared__ float xq[128], yq[128];
    __shared__ float sred[256];
    int tid = threadIdx.x;
    int zi = blockIdx.z;
    int i0 = blockIdx.y * 128, j0 = blockIdx.x * 128;
    const float* Ys  = zi ? g_neg  : g_pos;
    const float* Ysq = zi ? g_nsqn : g_psqn;
    for (int t = tid; t < 128 * 16; t += 256) {
        int r = t >> 4, c4 = (t & 15) * 4;
        float4 v = *(const float4*)&g_pos[(size_t)(i0 + r) * REDD + c4];
        Xsm[r*68+c4+0] = f2tf32(v.x); Xsm[r*68+c4+1] = f2tf32(v.y);
        Xsm[r*68+c4+2] = f2tf32(v.z); Xsm[r*68+c4+3] = f2tf32(v.w);
        float4 w = *(const float4*)&Ys[(size_t)(j0 + r) * REDD + c4];
        Ysm[r*68+c4+0] = f2tf32(w.x); Ysm[r*68+c4+1] = f2tf32(w.y);
        Ysm[r*68+c4+2] = f2tf32(w.z); Ysm[r*68+c4+3] = f2tf32(w.w);
    }
    if (tid < 128) { xq[tid] = g_psqn[i0 + tid]; yq[tid] = Ysq[j0 + tid]; }
    __syncthreads();

    int warp = tid >> 5, lane = tid & 31, gid = lane >> 2, tig = lane & 3;
    int wm = warp >> 2, wn = warp & 3;
    float acc[4][4][4];
    #pragma unroll
    for (int mt = 0; mt < 4; mt++)
        #pragma unroll
        for (int nt = 0; nt < 4; nt++)
            #pragma unroll
            for (int q = 0; q < 4; q++) acc[mt][nt][q] = 0.f;

    #pragma unroll
    for (int ks = 0; ks < 8; ks++) {
        int kb = ks * 8;
        unsigned a[4][4];
        #pragma unroll
        for (int mt = 0; mt < 4; mt++) {
            int R = wm * 64 + mt * 16;
            a[mt][0] = Xsm[(R+gid  )*68 + kb+tig];
            a[mt][1] = Xsm[(R+gid+8)*68 + kb+tig];
            a[mt][2] = Xsm[(R+gid  )*68 + kb+tig+4];
            a[mt][3] = Xsm[(R+gid+8)*68 + kb+tig+4];
        }
        #pragma unroll
        for (int nt = 0; nt < 4; nt++) {
            int Cb = wn * 32 + nt * 8;
            unsigned b0 = Ysm[(Cb+gid)*68 + kb+tig];
            unsigned b1 = Ysm[(Cb+gid)*68 + kb+tig+4];
            #pragma unroll
            for (int mt = 0; mt < 4; mt++)
                mma_tf32(acc[mt][nt], a[mt][0], a[mt][1], a[mt][2], a[mt][3], b0, b1);
        }
    }
    float lsum = 0.f;
    #pragma unroll
    for (int mt = 0; mt < 4; mt++)
        #pragma unroll
        for (int nt = 0; nt < 4; nt++)
            #pragma unroll
            for (int q = 0; q < 4; q++) {
                int il = wm*64 + mt*16 + gid + ((q >> 1) << 3);
                int jl = wn*32 + nt*8  + tig*2 + (q & 1);
                float sq = xq[il] + yq[jl] - 2.0f * acc[mt][nt][q];
                sq = fmaxf(sq, 0.f);
                float d = (sq > 0.f) ? sqrta(sq) : 0.f;
                lsum += __expf(-d);
            }
    sred[tid] = lsum;
    __syncthreads();
    for (int s2 = 128; s2 > 0; s2 >>= 1) {
        if (tid < s2) sred[tid] += sred[tid + s2];
        __syncthreads();
    }
    if (tid == 0) atomicAdd(zi ? &g_nsim : &g_psim, (double)sred[0]);
}

__global__ void k_loss(float* __restrict__ o)
{
    o[0] = (float)(log(g_nsim) - log(g_psim));
}

// ----------------------------- launcher --------------------------------------
extern "C" void kernel_launch(void* const* d_in, const int* in_sizes, int n_in,
                              void* d_out, int out_size)
{
    const float* A     = (const float*)d_in[0];
    const int*   C     = (const int*)  d_in[1];
    const float* L     = (const float*)d_in[2];
    const float* W1    = (const float*)d_in[3];
    const float* b1    = (const float*)d_in[4];
    const float* gamma = (const float*)d_in[5];
    const float* beta  = (const float*)d_in[6];
    const float* sigma = (const float*)d_in[7];
    const float* Pw    = (const float*)d_in[8];
    const float* Nw    = (const float*)d_in[9];
    const float* Wp1   = (const float*)d_in[10];
    const float* bp1   = (const float*)d_in[11];
    const float* Wp2   = (const float*)d_in[12];
    const float* bp2   = (const float*)d_in[13];
    const float* Wq1   = (const float*)d_in[14];
    const float* bq1   = (const float*)d_in[15];
    const float* Wq2   = (const float*)d_in[16];
    const float* bq2   = (const float*)d_in[17];
    const float* Wa    = (const float*)d_in[18];
    const float* ba    = (const float*)d_in[19];

    float* out   = (float*)d_out;
    float* outFF = out;                 // [4096*64]
    float* outL  = out + NN * REDD;     // [1]
    float* outD  = out + NN * REDD + 1; // [4096*4096], only 4B-aligned

    cudaFuncSetAttribute(k_fused, cudaFuncAttributeMaxDynamicSharedMemorySize, FUSED_SMEM_BYTES);
    cudaFuncSetAttribute(k_simmma, cudaFuncAttributeMaxDynamicSharedMemorySize, SIM_SMEM_BYTES);

    // k_fused is launch #4: the ncu window has landed on launch #4 every round.
    k_reset<<<1, 1>>>();
    k_interp<<<NN / 8, 256>>>(A, C, W1, b1);
    k_bnstats<<<64, 256>>>();
    k_fused<<<NN / 2, 256, FUSED_SMEM_BYTES>>>(L, C, Pw, Nw,
                                               Wp1, bp1, Wq1, bq1, Wa, ba,
                                               Wp2, bp2, Wq2, bq2, outFF);
    k_bnfin<<<1, 32>>>(gamma, beta);
    k_emb<<<NN / 8, 256>>>();
    k_d0<<<dim3(64, 64), 256>>>(sigma, outD);
    k_avg<<<1, 1>>>();
    k_dfinal<<<4096, 256>>>(outD);
    k_vecsqn<<<16, 256>>>();
    k_simmma<<<dim3(32, 32, 2), 256, SIM_SMEM_BYTES>>>();
    k_loss<<<1, 1>>>(outL);
}

// round 11
// speedup vs baseline: 1.1634x; 1.1528x over previous
#include <cuda_runtime.h>
#include <math.h>

#define NN   4096
#define SEQ  41
#define VEC  15
#define TT   8
#define EMBD 32
#define LDIM 256
#define REDD 64
#define BN_EPS 1e-5f
#define FLATD (TT*VEC)   // 120

// ------------------------- device scratch ------------------------------------
__device__ float  g_h[NN*EMBD];
__device__ double g_bns[EMBD], g_bnq[EMBD];
__device__ float  g_scale[EMBD], g_shift[EMBD];
__device__ float  g_emb[NN*EMBD];
__device__ float  g_sqn[NN];
__device__ double g_dsum;
__device__ float  g_avg, g_mn, g_invrange;
__device__ unsigned g_minbits, g_maxbits;
__device__ float  g_pos[NN*REDD], g_neg[NN*REDD];
__device__ float  g_psqn[NN], g_nsqn[NN];
__device__ double g_psim, g_nsim;

// ------------------------- helpers -------------------------------------------
__device__ __forceinline__ unsigned f2tf32(float x) {
    unsigned u; asm("cvt.rna.tf32.f32 %0, %1;" : "=r"(u) : "f"(x)); return u;
}
__device__ __forceinline__ float tanha(float x) {
    float y; asm("tanh.approx.f32 %0, %1;" : "=f"(y) : "f"(x)); return y;
}
__device__ __forceinline__ float sqrta(float x) {
    float y; asm("sqrt.approx.f32 %0, %1;" : "=f"(y) : "f"(x)); return y;
}
__device__ __forceinline__ void mma_tf32(float c[4],
    unsigned a0, unsigned a1, unsigned a2, unsigned a3,
    unsigned b0, unsigned b1)
{
    asm("mma.sync.aligned.m16n8k8.row.col.f32.tf32.tf32.f32 "
        "{%0,%1,%2,%3}, {%4,%5,%6,%7}, {%8,%9}, {%0,%1,%2,%3};"
        : "+f"(c[0]), "+f"(c[1]), "+f"(c[2]), "+f"(c[3])
        : "r"(a0), "r"(a1), "r"(a2), "r"(a3), "r"(b0), "r"(b1));
}
__device__ __forceinline__ void cp16(unsigned* smem_dst, const float* gsrc) {
    unsigned sa = (unsigned)__cvta_generic_to_shared(smem_dst);
    asm volatile("cp.async.cg.shared.global [%0], [%1], 16;" :: "r"(sa), "l"(gsrc));
}

// ------------------------- reset ---------------------------------------------
__global__ void k_reset() {
    g_dsum = 0.0; g_psim = 0.0; g_nsim = 0.0;
    g_minbits = 0x7f800000u;
    g_maxbits = 0u;
    for (int i = 0; i < EMBD; i++) { g_bns[i] = 0.0; g_bnq[i] = 0.0; }
}

// ---------------- interp gather + flat@W1 + tanh -> g_h ----------------------
__global__ void k_interp(const float* __restrict__ A, const int* __restrict__ C,
                         const float* __restrict__ W1, const float* __restrict__ b1)
{
    __shared__ float flat[8][128];
    __shared__ float w1s[FLATD * EMBD];
    int tid = threadIdx.x;
    for (int t = tid; t < FLATD * EMBD / 4; t += 256)
        *(float4*)&w1s[t * 4] = *(const float4*)&W1[t * 4];
    int warp = tid >> 5, lane = tid & 31;
    int n = blockIdx.x * 8 + warp;
    int st = C[2*n], en = C[2*n+1];
    int len = en - st + 1;
    float scale = (float)len / (float)TT;
    const float* Ar = A + (size_t)n * SEQ * VEC;
    for (int k = lane; k < FLATD; k += 32) {
        int j = k / VEC, v = k - j * VEC;
        float src = fmaxf(scale * ((float)j + 0.5f) - 0.5f, 0.0f);
        int i0 = min((int)floorf(src), len - 1);
        int i1 = min(i0 + 1, len - 1);
        float w = src - (float)i0;
        float g0 = Ar[(st + i0) * VEC + v];
        float g1 = Ar[(st + i1) * VEC + v];
        flat[warp][k] = (1.0f - w) * g0 + w * g1;
    }
    __syncthreads();
    int o = lane;
    float acc = b1[o];
    #pragma unroll 8
    for (int k = 0; k < FLATD; k++)
        acc = fmaf(flat[warp][k], w1s[k * EMBD + o], acc);
    g_h[n * EMBD + o] = tanhf(acc);
}

// ---------------- batchnorm stats -------------------------------------------
__global__ void k_bnstats()
{
    __shared__ float ss[8][32], sq2[8][32];
    int col = threadIdx.x & 31, seg = threadIdx.x >> 5;
    int r0 = blockIdx.x * 8 + seg;
    float s = 0.f, q = 0.f;
    for (int r = r0; r < NN; r += 512) {
        float h = g_h[r * EMBD + col];
        s += h; q = fmaf(h, h, q);
    }
    ss[seg][col] = s; sq2[seg][col] = q;
    __syncthreads();
    if (threadIdx.x < 32) {
        double S = 0.0, Q = 0.0;
        #pragma unroll
        for (int g = 0; g < 8; g++) { S += (double)ss[g][col]; Q += (double)sq2[g][col]; }
        atomicAdd(&g_bns[col], S);
        atomicAdd(&g_bnq[col], Q);
    }
}
__global__ void k_bnfin(const float* __restrict__ gamma, const float* __restrict__ beta)
{
    int col = threadIdx.x;
    float mu  = (float)(g_bns[col] / (double)NN);
    float var = (float)(g_bnq[col] / (double)NN) - mu * mu;
    float sc  = gamma[col] * rsqrtf(var + BN_EPS);
    g_scale[col] = sc;
    g_shift[col] = beta[col] - sc * mu;
}

// ---------------- emb + squared norms ----------------------------------------
__global__ void k_emb()
{
    int warp = threadIdx.x >> 5, lane = threadIdx.x & 31;
    int n = blockIdx.x * 8 + warp;
    float e = g_scale[lane] * g_h[n * EMBD + lane] + g_shift[lane];
    g_emb[n * EMBD + lane] = e;
    float s = e * e;
    #pragma unroll
    for (int o = 16; o > 0; o >>= 1) s += __shfl_xor_sync(0xffffffffu, s, o);
    if (lane == 0) g_sqn[n] = s;
}

// ========== k_fused: cp.async double-buffered proj1 + proj2 + means ==========
// 256 threads, 8 warps, warp grid 2(M)x4(N), warp tile 48x48 (3mt x 6nt).
// A/B staged raw fp32 (mma.tf32 truncates); double buffer; 1 sync per chunk.
#define A_WORDS 3456              // 96*36
#define B_WORDS 6400              // 32*200
#define OFF_A   0                 // 2 buffers: 6912
#define OFF_B   6912              // 2 buffers: 12800 -> ends 19712
#define OFF_HP  19712             // 96*68 = 6528
#define OFF_HQ  26240             // 6528 -> 32768
#define OFF_WPS 32768
#define OFF_WNS 32864
#define OFF_BSH 32960
#define OFF_FF  33152
#define OFF_PS  33280
#define FUSED_SMEM_BYTES (33408 * 4)   // 133,632 B

__global__ void __launch_bounds__(256) k_fused(
    const float* __restrict__ L, const int* __restrict__ C,
    const float* __restrict__ Pw, const float* __restrict__ Nw,
    const float* __restrict__ Wp1, const float* __restrict__ bp1,
    const float* __restrict__ Wq1, const float* __restrict__ bq1,
    const float* __restrict__ Wa,  const float* __restrict__ ba,
    const float* __restrict__ Wp2, const float* __restrict__ bp2,
    const float* __restrict__ Wq2, const float* __restrict__ bq2,
    float* __restrict__ outFF)
{
    extern __shared__ float sm[];
    unsigned* Abuf = (unsigned*)(sm + OFF_A);
    unsigned* Bbuf = (unsigned*)(sm + OFF_B);
    unsigned* HPs  = (unsigned*)(sm + OFF_HP);
    unsigned* HQs  = (unsigned*)(sm + OFF_HQ);
    float* wps = sm + OFF_WPS;
    float* wns = sm + OFF_WNS;
    float* bsh = sm + OFF_BSH;
    float* FF  = sm + OFF_FF;
    float* PS  = sm + OFF_PS;

    int tid = threadIdx.x;
    int n0 = blockIdx.x * 2;
    size_t rb = (size_t)n0 * SEQ;

    if (tid < 128) { FF[tid] = 0.f; PS[tid] = 0.f; }
    if (tid < 96) {
        float vp = 0.f, vn = 0.f;
        if (tid < 82) {
            int nl = (tid >= 41);
            int nnx = n0 + nl, s = tid - nl * 41;
            int st = C[2*nnx], en = C[2*nnx+1];
            bool pm = (s >= st && s <= en);
            vp = pm ? Pw[nnx * SEQ + s] : 0.f;
            vn = pm ? 0.f : Nw[nnx * SEQ + s];
        }
        wps[tid] = vp; wns[tid] = vn;
    }
    for (int j = tid; j < 192; j += 256)
        bsh[j] = (j < 64) ? bp1[j] : (j < 128 ? bq1[j - 64] : ba[j - 128]);

    int warp = tid >> 5, lane = tid & 31, gid = lane >> 2, tig = lane & 3;
    int wm = warp >> 2, wn = warp & 3;   // 2(M) x 4(N)

    // per-thread staging coords (fixed)
    int sr0 = tid >> 3, sc4 = (tid & 7) * 4;

    float acc[3][6][4];
    #pragma unroll
    for (int mt = 0; mt < 3; mt++)
        #pragma unroll
        for (int nt = 0; nt < 6; nt++)
            #pragma unroll
            for (int q = 0; q < 4; q++) acc[mt][nt][q] = 0.f;

    // ---- async stage of chunk (k0) into buffer bi ----
    #define STAGE_CHUNK(k0, bi) do {                                           \
        unsigned* Ad = Abuf + (bi) * A_WORDS;                                  \
        unsigned* Bd = Bbuf + (bi) * B_WORDS;                                  \
        _Pragma("unroll")                                                      \
        for (int i = 0; i < 3; i++) {                                          \
            int rr = sr0 + i * 32;                                             \
            int gr = (rr < 82) ? rr : 81;                                      \
            cp16(Ad + rr*36 + sc4, &L[(rb + gr) * LDIM + (k0) + sc4]);         \
        }                                                                      \
        _Pragma("unroll")                                                      \
        for (int i = 0; i < 6; i++) {                                          \
            int t = tid + i * 256;                                             \
            int k = t / 48, q2 = t - k * 48;                                   \
            int n = q2 * 4;                                                    \
            int grp = n >> 6, jj = n & 63;                                     \
            const float* src = (grp == 0) ? Wp1 : (grp == 1 ? Wq1 : Wa);       \
            cp16(Bd + k*200 + n, &src[((k0) + k) * 64 + jj]);                  \
        }                                                                      \
        asm volatile("cp.async.commit_group;" ::: "memory");                   \
    } while (0)

    STAGE_CHUNK(0, 0);
    for (int c = 0; c < 8; c++) {
        asm volatile("cp.async.wait_group 0;" ::: "memory");
        __syncthreads();
        if (c < 7) STAGE_CHUNK((c + 1) * 32, (c + 1) & 1);
        const unsigned* As = Abuf + (c & 1) * A_WORDS;
        const unsigned* Bs = Bbuf + (c & 1) * B_WORDS;
        #pragma unroll
        for (int ks = 0; ks < 4; ks++) {
            int kb = ks * 8;
            unsigned a[3][4];
            #pragma unroll
            for (int mt = 0; mt < 3; mt++) {
                int R = wm * 48 + mt * 16;
                a[mt][0] = As[(R+gid  )*36 + kb+tig];
                a[mt][1] = As[(R+gid+8)*36 + kb+tig];
                a[mt][2] = As[(R+gid  )*36 + kb+tig+4];
                a[mt][3] = As[(R+gid+8)*36 + kb+tig+4];
            }
            #pragma unroll
            for (int nt = 0; nt < 6; nt++) {
                int Cb = wn * 48 + nt * 8;
                unsigned b0 = Bs[(kb+tig  )*200 + Cb+gid];
                unsigned b1 = Bs[(kb+tig+4)*200 + Cb+gid];
                #pragma unroll
                for (int mt = 0; mt < 3; mt++)
                    mma_tf32(acc[mt][nt], a[mt][0], a[mt][1], a[mt][2], a[mt][3], b0, b1);
            }
        }
    }

    // stage1 epilogue: weights + bias + tanh -> HP/HQ smem (tf32) + FF sums
    #pragma unroll
    for (int mt = 0; mt < 3; mt++) {
        #pragma unroll
        for (int half = 0; half < 2; half++) {
            int r = wm * 48 + mt * 16 + gid + half * 8;
            bool valid = (r < 82);
            int nl = (r >= 41) ? 1 : 0;
            float wp = wps[r], wq = wns[r];
            #pragma unroll
            for (int nt = 0; nt < 6; nt++) {
                int j0 = wn * 48 + nt * 8 + tig * 2;
                int grp = j0 >> 6, jj = j0 & 63;
                float w = (grp == 0) ? wp : (grp == 1 ? wq : wp + wq);
                float v0 = tanha(fmaf(w, acc[mt][nt][half*2+0], bsh[j0]));
                float v1 = tanha(fmaf(w, acc[mt][nt][half*2+1], bsh[j0+1]));
                if (grp == 0)      { HPs[r*68+jj] = f2tf32(v0); HPs[r*68+jj+1] = f2tf32(v1); }
                else if (grp == 1) { HQs[r*68+jj] = f2tf32(v0); HQs[r*68+jj+1] = f2tf32(v1); }
                else if (valid) {
                    atomicAdd(&FF[nl*64 + jj],     v0);
                    atomicAdd(&FF[nl*64 + jj + 1], v1);
                }
            }
        }
    }
    __syncthreads();
    if (tid < 128) {
        int nl = tid >> 6, c = tid & 63;
        outFF[(size_t)(n0 + nl) * 64 + c] = FF[tid] * (1.0f / 41.0f);
    }

    // ---- stage 2: (96x64)@(64x64) per p; W2 via cp.async; warp grid 2x4 ----
    for (int p = 0; p < 2; p++) {
        const float* W2 = p ? Wq2 : Wp2;
        const float* b2 = p ? bq2 : bp2;
        const unsigned* H = p ? HQs : HPs;
        float* outv = p ? g_neg : g_pos;
        __syncthreads();
        for (int t = tid; t < 1024; t += 256) {
            int k = t >> 4, n = (t & 15) * 4;
            cp16(Bbuf + k*72 + n, &W2[k * 64 + n]);
        }
        asm volatile("cp.async.commit_group;" ::: "memory");
        if (tid < 64) bsh[tid] = b2[tid];
        asm volatile("cp.async.wait_group 0;" ::: "memory");
        __syncthreads();

        float acc2[3][2][4];
        #pragma unroll
        for (int mt = 0; mt < 3; mt++)
            #pragma unroll
            for (int nt = 0; nt < 2; nt++)
                #pragma unroll
                for (int q = 0; q < 4; q++) acc2[mt][nt][q] = 0.f;

        #pragma unroll
        for (int ks = 0; ks < 8; ks++) {
            int kb = ks * 8;
            unsigned a[3][4];
            #pragma unroll
            for (int mt = 0; mt < 3; mt++) {
                int R = wm * 48 + mt * 16;
                a[mt][0] = H[(R+gid  )*68 + kb+tig];
                a[mt][1] = H[(R+gid+8)*68 + kb+tig];
                a[mt][2] = H[(R+gid  )*68 + kb+tig+4];
                a[mt][3] = H[(R+gid+8)*68 + kb+tig+4];
            }
            #pragma unroll
            for (int nt = 0; nt < 2; nt++) {
                int Cb = wn * 16 + nt * 8;
                unsigned b0 = Bbuf[(kb+tig  )*72 + Cb+gid];
                unsigned b1 = Bbuf[(kb+tig+4)*72 + Cb+gid];
                #pragma unroll
                for (int mt = 0; mt < 3; mt++)
                    mma_tf32(acc2[mt][nt], a[mt][0], a[mt][1], a[mt][2], a[mt][3], b0, b1);
            }
        }
        #pragma unroll
        for (int mt = 0; mt < 3; mt++)
            #pragma unroll
            for (int half = 0; half < 2; half++) {
                int r = wm * 48 + mt * 16 + gid + half * 8;
                bool valid = (r < 82);
                int nl = (r >= 41) ? 1 : 0;
                #pragma unroll
                for (int nt = 0; nt < 2; nt++) {
                    int j = wn * 16 + nt * 8 + tig * 2;
                    float v0 = tanha(acc2[mt][nt][half*2+0] + bsh[j]);
                    float v1 = tanha(acc2[mt][nt][half*2+1] + bsh[j+1]);
                    if (valid) {
                        atomicAdd(&PS[nl*64 + j],     v0);
                        atomicAdd(&PS[nl*64 + j + 1], v1);
                    }
                }
            }
        __syncthreads();
        if (tid < 128) {
            int nl = tid >> 6, c = tid & 63;
            outv[(size_t)(n0 + nl) * 64 + c] = PS[tid] * (1.0f / 41.0f);
            PS[tid] = 0.f;
        }
    }
    #undef STAGE_CHUNK
}

// ---------------- D0: scalar fp32 gram + sum + RAW minmax --------------------
__global__ void __launch_bounds__(256) k_d0(const float* __restrict__ sigma,
                                            float* __restrict__ outD)
{
    __shared__ float Ei[64][33], Ej[64][33];
    __shared__ float sred[256];
    __shared__ unsigned smn[256], smx[256];
    int i0 = blockIdx.y * 64, j0 = blockIdx.x * 64;
    int tid = threadIdx.x;
    for (int t = tid; t < 64 * 32; t += 256) {
        int r = t >> 5, c = t & 31;
        Ei[r][c] = g_emb[(i0 + r) * EMBD + c];
        Ej[r][c] = g_emb[(j0 + r) * EMBD + c];
    }
    __syncthreads();
    float inv = 1.0f / (2.0f * sigma[0] * sigma[0]);
    int tx = tid & 15, ty = tid >> 4;
    float acc[4][4];
    #pragma unroll
    for (int a = 0; a < 4; a++)
        #pragma unroll
        for (int b = 0; b < 4; b++) acc[a][b] = 0.0f;
    #pragma unroll 4
    for (int k = 0; k < 32; k++) {
        float av[4], bv[4];
        #pragma unroll
        for (int a = 0; a < 4; a++) av[a] = Ei[ty * 4 + a][k];
        #pragma unroll
        for (int b = 0; b < 4; b++) bv[b] = Ej[tx * 4 + b][k];
        #pragma unroll
        for (int a = 0; a < 4; a++)
            #pragma unroll
            for (int b = 0; b < 4; b++) acc[a][b] = fmaf(av[a], bv[b], acc[a][b]);
    }
    float lsum = 0.0f;
    unsigned mn = 0x7f800000u, mx = 0u;
    #pragma unroll
    for (int a = 0; a < 4; a++) {
        int i = i0 + ty * 4 + a;
        float si = g_sqn[i];
        #pragma unroll
        for (int b = 0; b < 4; b++) {
            int j = j0 + tx * 4 + b;
            float sqv = si + g_sqn[j] - 2.0f * acc[a][b];
            sqv = fmaxf(sqv, 0.0f);
            float d = (sqv > 0.0f) ? sqrta(sqv) : 0.0f;
            float e = __expf(-d * inv);
            if (i != j) {
                lsum += e;
                unsigned bb = __float_as_uint(e);
                mn = min(mn, bb); mx = max(mx, bb);
            }
            outD[(size_t)i * NN + (size_t)j] = e;
        }
    }
    sred[tid] = lsum; smn[tid] = mn; smx[tid] = mx;
    __syncthreads();
    for (int s2 = 128; s2 > 0; s2 >>= 1) {
        if (tid < s2) {
            sred[tid] += sred[tid + s2];
            smn[tid] = min(smn[tid], smn[tid + s2]);
            smx[tid] = max(smx[tid], smx[tid + s2]);
        }
        __syncthreads();
    }
    if (tid == 0) {
        atomicAdd(&g_dsum, (double)sred[0]);
        atomicMin(&g_minbits, smn[0]);
        atomicMax(&g_maxbits, smx[0]);
    }
}

__global__ void k_avg() {
    float avg = (float)(g_dsum / ((double)NN * (double)(NN - 1)));
    g_avg = avg;
    float mnr = __uint_as_float(g_minbits);
    float mxr = __uint_as_float(g_maxbits);
    float mn = (mnr < avg) ? 0.0f : mnr;
    float mx = mxr;
    if (mx == mn) mx = mn + 1.0f;
    g_mn = mn; g_invrange = 1.0f / (mx - mn);
}

__global__ void k_dfinal(float* __restrict__ outD)
{
    float avg = g_avg, mn = g_mn, inv = g_invrange;
    long long total = (long long)NN * NN;
    for (long long idx = (long long)blockIdx.x * blockDim.x + threadIdx.x; idx < total;
         idx += (long long)gridDim.x * blockDim.x) {
        int i = (int)(idx >> 12), j = (int)(idx & (NN - 1));
        float d = outD[idx];
        float t = (d < avg) ? 0.0f : d;
        float v = (t - mn) * inv;
        if (i == j) v = 1.0f;
        outD[idx] = v;
    }
}

__global__ void k_vecsqn()
{
    int n = blockIdx.x * blockDim.x + threadIdx.x;
    if (n >= NN) return;
    float a = 0.0f, b = 0.0f;
    #pragma unroll 8
    for (int o = 0; o < REDD; o++) {
        float p = g_pos[n * REDD + o]; a = fmaf(p, p, a);
        float q = g_neg[n * REDD + o]; b = fmaf(q, q, b);
    }
    g_psqn[n] = a; g_nsqn[n] = b;
}

// ========== k_simmma: 128x128 tiles of exp(-cdist) sums via tf32 mma ========
#define SIM_SMEM_BYTES (2 * 128 * 68 * 4)
__global__ void __launch_bounds__(256) k_simmma()
{
    extern __shared__ unsigned simsm[];
    unsigned* Xsm = simsm;
    unsigned* Ysm = simsm + 128 * 68;
    __shared__ float xq[128], yq[128];
    __shared__ float sred[256];
    int tid = threadIdx.x;
    int zi = blockIdx.z;
    int i0 = blockIdx.y * 128, j0 = blockIdx.x * 128;
    const float* Ys  = zi ? g_neg  : g_pos;
    const float* Ysq = zi ? g_nsqn : g_psqn;
    for (int t = tid; t < 128 * 16; t += 256) {
        int r = t >> 4, c4 = (t & 15) * 4;
        float4 v = *(const float4*)&g_pos[(size_t)(i0 + r) * REDD + c4];
        Xsm[r*68+c4+0] = f2tf32(v.x); Xsm[r*68+c4+1] = f2tf32(v.y);
        Xsm[r*68+c4+2] = f2tf32(v.z); Xsm[r*68+c4+3] = f2tf32(v.w);
        float4 w = *(const float4*)&Ys[(size_t)(j0 + r) * REDD + c4];
        Ysm[r*68+c4+0] = f2tf32(w.x); Ysm[r*68+c4+1] = f2tf32(w.y);
        Ysm[r*68+c4+2] = f2tf32(w.z); Ysm[r*68+c4+3] = f2tf32(w.w);
    }
    if (tid < 128) { xq[tid] = g_psqn[i0 + tid]; yq[tid] = Ysq[j0 + tid]; }
    __syncthreads();

    int warp = tid >> 5, lane = tid & 31, gid = lane >> 2, tig = lane & 3;
    int wm = warp >> 2, wn = warp & 3;
    float acc[4][4][4];
    #pragma unroll
    for (int mt = 0; mt < 4; mt++)
        #pragma unroll
        for (int nt = 0; nt < 4; nt++)
            #pragma unroll
            for (int q = 0; q < 4; q++) acc[mt][nt][q] = 0.f;

    #pragma unroll
    for (int ks = 0; ks < 8; ks++) {
        int kb = ks * 8;
        unsigned a[4][4];
        #pragma unroll
        for (int mt = 0; mt < 4; mt++) {
            int R = wm * 64 + mt * 16;
            a[mt][0] = Xsm[(R+gid  )*68 + kb+tig];
            a[mt][1] = Xsm[(R+gid+8)*68 + kb+tig];
            a[mt][2] = Xsm[(R+gid  )*68 + kb+tig+4];
            a[mt][3] = Xsm[(R+gid+8)*68 + kb+tig+4];
        }
        #pragma unroll
        for (int nt = 0; nt < 4; nt++) {
            int Cb = wn * 32 + nt * 8;
            unsigned b0 = Ysm[(Cb+gid)*68 + kb+tig];
            unsigned b1 = Ysm[(Cb+gid)*68 + kb+tig+4];
            #pragma unroll
            for (int mt = 0; mt < 4; mt++)
                mma_tf32(acc[mt][nt], a[mt][0], a[mt][1], a[mt][2], a[mt][3], b0, b1);
        }
    }
    float lsum = 0.f;
    #pragma unroll
    for (int mt = 0; mt < 4; mt++)
        #pragma unroll
        for (int nt = 0; nt < 4; nt++)
            #pragma unroll
            for (int q = 0; q < 4; q++) {
                int il = wm*64 + mt*16 + gid + ((q >> 1) << 3);
                int jl = wn*32 + nt*8  + tig*2 + (q & 1);
                float sq = xq[il] + yq[jl] - 2.0f * acc[mt][nt][q];
                sq = fmaxf(sq, 0.f);
                float d = (sq > 0.f) ? sqrta(sq) : 0.f;
                lsum += __expf(-d);
            }
    sred[tid] = lsum;
    __syncthreads();
    for (int s2 = 128; s2 > 0; s2 >>= 1) {
        if (tid < s2) sred[tid] += sred[tid + s2];
        __syncthreads();
    }
    if (tid == 0) atomicAdd(zi ? &g_nsim : &g_psim, (double)sred[0]);
}

__global__ void k_loss(float* __restrict__ o)
{
    o[0] = (float)(log(g_nsim) - log(g_psim));
}

// ----------------------------- launcher --------------------------------------
extern "C" void kernel_launch(void* const* d_in, const int* in_sizes, int n_in,
                              void* d_out, int out_size)
{
    const float* A     = (const float*)d_in[0];
    const int*   C     = (const int*)  d_in[1];
    const float* L     = (const float*)d_in[2];
    const float* W1    = (const float*)d_in[3];
    const float* b1    = (const float*)d_in[4];
    const float* gamma = (const float*)d_in[5];
    const float* beta  = (const float*)d_in[6];
    const float* sigma = (const float*)d_in[7];
    const float* Pw    = (const float*)d_in[8];
    const float* Nw    = (const float*)d_in[9];
    const float* Wp1   = (const float*)d_in[10];
    const float* bp1   = (const float*)d_in[11];
    const float* Wp2   = (const float*)d_in[12];
    const float* bp2   = (const float*)d_in[13];
    const float* Wq1   = (const float*)d_in[14];
    const float* bq1   = (const float*)d_in[15];
    const float* Wq2   = (const float*)d_in[16];
    const float* bq2   = (const float*)d_in[17];
    const float* Wa    = (const float*)d_in[18];
    const float* ba    = (const float*)d_in[19];

    float* out   = (float*)d_out;
    float* outFF = out;                 // [4096*64]
    float* outL  = out + NN * REDD;     // [1]
    float* outD  = out + NN * REDD + 1; // [4096*4096], only 4B-aligned

    cudaFuncSetAttribute(k_fused, cudaFuncAttributeMaxDynamicSharedMemorySize, FUSED_SMEM_BYTES);
    cudaFuncSetAttribute(k_simmma, cudaFuncAttributeMaxDynamicSharedMemorySize, SIM_SMEM_BYTES);

    // k_fused at launch #4: the ncu window lands on launch #4.
    k_reset<<<1, 1>>>();
    k_interp<<<NN / 8, 256>>>(A, C, W1, b1);
    k_bnstats<<<64, 256>>>();
    k_fused<<<NN / 2, 256, FUSED_SMEM_BYTES>>>(L, C, Pw, Nw,
                                               Wp1, bp1, Wq1, bq1, Wa, ba,
                                               Wp2, bp2, Wq2, bq2, outFF);
    k_bnfin<<<1, 32>>>(gamma, beta);
    k_emb<<<NN / 8, 256>>>();
    k_d0<<<dim3(64, 64), 256>>>(sigma, outD);
    k_avg<<<1, 1>>>();
    k_dfinal<<<4096, 256>>>(outD);
    k_vecsqn<<<16, 256>>>();
    k_simmma<<<dim3(32, 32, 2), 256, SIM_SMEM_BYTES>>>();
    k_loss<<<1, 1>>>(outL);
}

// round 14
// speedup vs baseline: 1.7778x; 1.5281x over previous
#include <cuda_runtime.h>
#include <cuda_fp16.h>
#include <math.h>

#define NN   4096
#define SEQ  41
#define VEC  15
#define TT   8
#define EMBD 32
#define LDIM 256
#define REDD 64
#define BN_EPS 1e-5f
#define FLATD (TT*VEC)   // 120

// ------------------------- device scratch ------------------------------------
__device__ float  g_h[NN*EMBD];
__device__ double g_bns[EMBD], g_bnq[EMBD];
__device__ float  g_scale[EMBD], g_shift[EMBD];
__device__ float  g_emb[NN*EMBD];
__device__ float  g_sqn[NN];
__device__ double g_dsum;
__device__ float  g_avg, g_mn, g_invrange;
__device__ unsigned g_minbits, g_maxbits;
__device__ float  g_pos[NN*REDD], g_neg[NN*REDD];
__device__ float  g_psqn[NN], g_nsqn[NN];
__device__ double g_psim, g_nsim;

// ------------------------- helpers -------------------------------------------
__device__ __forceinline__ unsigned f2tf32(float x) {
    unsigned u; asm("cvt.rna.tf32.f32 %0, %1;" : "=r"(u) : "f"(x)); return u;
}
__device__ __forceinline__ float tanha(float x) {
    float y; asm("tanh.approx.f32 %0, %1;" : "=f"(y) : "f"(x)); return y;
}
__device__ __forceinline__ float sqrta(float x) {
    float y; asm("sqrt.approx.f32 %0, %1;" : "=f"(y) : "f"(x)); return y;
}
__device__ __forceinline__ void mma_tf32(float c[4],
    unsigned a0, unsigned a1, unsigned a2, unsigned a3,
    unsigned b0, unsigned b1)
{
    asm("mma.sync.aligned.m16n8k8.row.col.f32.tf32.tf32.f32 "
        "{%0,%1,%2,%3}, {%4,%5,%6,%7}, {%8,%9}, {%0,%1,%2,%3};"
        : "+f"(c[0]), "+f"(c[1]), "+f"(c[2]), "+f"(c[3])
        : "r"(a0), "r"(a1), "r"(a2), "r"(a3), "r"(b0), "r"(b1));
}
__device__ __forceinline__ void mma_f16(float c[4],
    unsigned a0, unsigned a1, unsigned a2, unsigned a3,
    unsigned b0, unsigned b1)
{
    asm("mma.sync.aligned.m16n8k16.row.col.f32.f16.f16.f32 "
        "{%0,%1,%2,%3}, {%4,%5,%6,%7}, {%8,%9}, {%0,%1,%2,%3};"
        : "+f"(c[0]), "+f"(c[1]), "+f"(c[2]), "+f"(c[3])
        : "r"(a0), "r"(a1), "r"(a2), "r"(a3), "r"(b0), "r"(b1));
}
__device__ __forceinline__ void cp16(void* smem_dst, const float* gsrc) {
    unsigned sa = (unsigned)__cvta_generic_to_shared(smem_dst);
    asm volatile("cp.async.cg.shared.global [%0], [%1], 16;" :: "r"(sa), "l"(gsrc));
}

// ------------------------- reset ---------------------------------------------
__global__ void k_reset() {
    g_dsum = 0.0; g_psim = 0.0; g_nsim = 0.0;
    g_minbits = 0x7f800000u;
    g_maxbits = 0u;
    for (int i = 0; i < EMBD; i++) { g_bns[i] = 0.0; g_bnq[i] = 0.0; }
}

// ---------------- interp gather + flat@W1 + tanh -> g_h ----------------------
__global__ void k_interp(const float* __restrict__ A, const int* __restrict__ C,
                         const float* __restrict__ W1, const float* __restrict__ b1)
{
    __shared__ float flat[8][128];
    __shared__ float w1s[FLATD * EMBD];
    int tid = threadIdx.x;
    for (int t = tid; t < FLATD * EMBD / 4; t += 256)
        *(float4*)&w1s[t * 4] = *(const float4*)&W1[t * 4];
    int warp = tid >> 5, lane = tid & 31;
    int n = blockIdx.x * 8 + warp;
    int st = C[2*n], en = C[2*n+1];
    int len = en - st + 1;
    float scale = (float)len / (float)TT;
    const float* Ar = A + (size_t)n * SEQ * VEC;
    for (int k = lane; k < FLATD; k += 32) {
        int j = k / VEC, v = k - j * VEC;
        float src = fmaxf(scale * ((float)j + 0.5f) - 0.5f, 0.0f);
        int i0 = min((int)floorf(src), len - 1);
        int i1 = min(i0 + 1, len - 1);
        float w = src - (float)i0;
        float g0 = Ar[(st + i0) * VEC + v];
        float g1 = Ar[(st + i1) * VEC + v];
        flat[warp][k] = (1.0f - w) * g0 + w * g1;
    }
    __syncthreads();
    int o = lane;
    float acc = b1[o];
    #pragma unroll 8
    for (int k = 0; k < FLATD; k++)
        acc = fmaf(flat[warp][k], w1s[k * EMBD + o], acc);
    g_h[n * EMBD + o] = tanhf(acc);
}

// ---------------- batchnorm stats -------------------------------------------
__global__ void k_bnstats()
{
    __shared__ float ss[8][32], sq2[8][32];
    int col = threadIdx.x & 31, seg = threadIdx.x >> 5;
    int r0 = blockIdx.x * 8 + seg;
    float s = 0.f, q = 0.f;
    for (int r = r0; r < NN; r += 512) {
        float h = g_h[r * EMBD + col];
        s += h; q = fmaf(h, h, q);
    }
    ss[seg][col] = s; sq2[seg][col] = q;
    __syncthreads();
    if (threadIdx.x < 32) {
        double S = 0.0, Q = 0.0;
        #pragma unroll
        for (int g = 0; g < 8; g++) { S += (double)ss[g][col]; Q += (double)sq2[g][col]; }
        atomicAdd(&g_bns[col], S);
        atomicAdd(&g_bnq[col], Q);
    }
}
__global__ void k_bnfin(const float* __restrict__ gamma, const float* __restrict__ beta)
{
    int col = threadIdx.x;
    float mu  = (float)(g_bns[col] / (double)NN);
    float var = (float)(g_bnq[col] / (double)NN) - mu * mu;
    float sc  = gamma[col] * rsqrtf(var + BN_EPS);
    g_scale[col] = sc;
    g_shift[col] = beta[col] - sc * mu;
}

// ---------------- emb + squared norms ----------------------------------------
__global__ void k_emb()
{
    int warp = threadIdx.x >> 5, lane = threadIdx.x & 31;
    int n = blockIdx.x * 8 + warp;
    float e = g_scale[lane] * g_h[n * EMBD + lane] + g_shift[lane];
    g_emb[n * EMBD + lane] = e;
    float s = e * e;
    #pragma unroll
    for (int o = 16; o > 0; o >>= 1) s += __shfl_xor_sync(0xffffffffu, s, o);
    if (lane == 0) g_sqn[n] = s;
}

// ========== k_fused: cp.async proj1 (tf32) + proj2 (fp16) + means ============
// 256 threads, 8 warps, stage1 warp grid 2(M)x4(N), warp tile 48x48.
// HP/HQ stored fp16 (row pad 72 halfs = 36 words) -> smem 109KB -> 2 CTAs/SM.
#define A_WORDS 3456              // 96*36
#define B_WORDS 6400              // 32*200
#define OFF_A   0                 // 2 buffers: 6912
#define OFF_B   6912              // 2 buffers: 12800 -> 19712
#define OFF_HP  19712             // fp16 96*72 -> 3456 words
#define OFF_HQ  23168             // 3456 -> 26624
#define OFF_WPS 26624
#define OFF_WNS 26720
#define OFF_BSH 26816
#define OFF_FF  27008
#define OFF_PS  27136
#define FUSED_SMEM_BYTES (27264 * 4)   // 109,056 B

__global__ void __launch_bounds__(256, 2) k_fused(
    const float* __restrict__ L, const int* __restrict__ C,
    const float* __restrict__ Pw, const float* __restrict__ Nw,
    const float* __restrict__ Wp1, const float* __restrict__ bp1,
    const float* __restrict__ Wq1, const float* __restrict__ bq1,
    const float* __restrict__ Wa,  const float* __restrict__ ba,
    const float* __restrict__ Wp2, const float* __restrict__ bp2,
    const float* __restrict__ Wq2, const float* __restrict__ bq2,
    float* __restrict__ outFF)
{
    extern __shared__ float sm[];
    unsigned* Abuf = (unsigned*)(sm + OFF_A);
    unsigned* Bbuf = (unsigned*)(sm + OFF_B);
    __half*  HPh  = (__half*)(sm + OFF_HP);
    __half*  HQh  = (__half*)(sm + OFF_HQ);
    float* wps = sm + OFF_WPS;
    float* wns = sm + OFF_WNS;
    float* bsh = sm + OFF_BSH;
    float* FF  = sm + OFF_FF;
    float* PS  = sm + OFF_PS;

    int tid = threadIdx.x;
    int n0 = blockIdx.x * 2;
    size_t rb = (size_t)n0 * SEQ;

    if (tid < 128) { FF[tid] = 0.f; PS[tid] = 0.f; }
    if (tid < 96) {
        float vp = 0.f, vn = 0.f;
        if (tid < 82) {
            int nl = (tid >= 41);
            int nnx = n0 + nl, s = tid - nl * 41;
            int st = C[2*nnx], en = C[2*nnx+1];
            bool pm = (s >= st && s <= en);
            vp = pm ? Pw[nnx * SEQ + s] : 0.f;
            vn = pm ? 0.f : Nw[nnx * SEQ + s];
        }
        wps[tid] = vp; wns[tid] = vn;
    }
    for (int j = tid; j < 192; j += 256)
        bsh[j] = (j < 64) ? bp1[j] : (j < 128 ? bq1[j - 64] : ba[j - 128]);

    int warp = tid >> 5, lane = tid & 31, gid = lane >> 2, tig = lane & 3;
    int wm = warp >> 2, wn = warp & 3;   // 2(M) x 4(N)

    int sr0 = tid >> 3, sc4 = (tid & 7) * 4;

    float acc[3][6][4];
    #pragma unroll
    for (int mt = 0; mt < 3; mt++)
        #pragma unroll
        for (int nt = 0; nt < 6; nt++)
            #pragma unroll
            for (int q = 0; q < 4; q++) acc[mt][nt][q] = 0.f;

    #define STAGE_CHUNK(k0, bi) do {                                           \
        unsigned* Ad = Abuf + (bi) * A_WORDS;                                  \
        unsigned* Bd = Bbuf + (bi) * B_WORDS;                                  \
        _Pragma("unroll")                                                      \
        for (int i = 0; i < 3; i++) {                                          \
            int rr = sr0 + i * 32;                                             \
            int gr = (rr < 82) ? rr : 81;                                      \
            cp16(Ad + rr*36 + sc4, &L[(rb + gr) * LDIM + (k0) + sc4]);         \
        }                                                                      \
        _Pragma("unroll")                                                      \
        for (int i = 0; i < 6; i++) {                                          \
            int t = tid + i * 256;                                             \
            int k = t / 48, q2 = t - k * 48;                                   \
            int n = q2 * 4;                                                    \
            int grp = n >> 6, jj = n & 63;                                     \
            const float* src = (grp == 0) ? Wp1 : (grp == 1 ? Wq1 : Wa);       \
            cp16(Bd + k*200 + n, &src[((k0) + k) * 64 + jj]);                  \
        }                                                                      \
        asm volatile("cp.async.commit_group;" ::: "memory");                   \
    } while (0)

    STAGE_CHUNK(0, 0);
    for (int c = 0; c < 8; c++) {
        asm volatile("cp.async.wait_group 0;" ::: "memory");
        __syncthreads();
        if (c < 7) STAGE_CHUNK((c + 1) * 32, (c + 1) & 1);
        const unsigned* As = Abuf + (c & 1) * A_WORDS;
        const unsigned* Bs = Bbuf + (c & 1) * B_WORDS;
        #pragma unroll
        for (int ks = 0; ks < 4; ks++) {
            int kb = ks * 8;
            unsigned a[3][4];
            #pragma unroll
            for (int mt = 0; mt < 3; mt++) {
                int R = wm * 48 + mt * 16;
                a[mt][0] = As[(R+gid  )*36 + kb+tig];
                a[mt][1] = As[(R+gid+8)*36 + kb+tig];
                a[mt][2] = As[(R+gid  )*36 + kb+tig+4];
                a[mt][3] = As[(R+gid+8)*36 + kb+tig+4];
            }
            #pragma unroll
            for (int nt = 0; nt < 6; nt++) {
                int Cb = wn * 48 + nt * 8;
                unsigned b0 = Bs[(kb+tig  )*200 + Cb+gid];
                unsigned b1 = Bs[(kb+tig+4)*200 + Cb+gid];
                #pragma unroll
                for (int mt = 0; mt < 3; mt++)
                    mma_tf32(acc[mt][nt], a[mt][0], a[mt][1], a[mt][2], a[mt][3], b0, b1);
            }
        }
    }

    // stage1 epilogue: weights + bias + tanh -> HP/HQ (fp16) + FF sums
    #pragma unroll
    for (int mt = 0; mt < 3; mt++) {
        #pragma unroll
        for (int half2i = 0; half2i < 2; half2i++) {
            int r = wm * 48 + mt * 16 + gid + half2i * 8;
            bool valid = (r < 82);
            int nl = (r >= 41) ? 1 : 0;
            float wp = wps[r], wq = wns[r];
            #pragma unroll
            for (int nt = 0; nt < 6; nt++) {
                int j0 = wn * 48 + nt * 8 + tig * 2;
                int grp = j0 >> 6, jj = j0 & 63;
                float w = (grp == 0) ? wp : (grp == 1 ? wq : wp + wq);
                float v0 = tanha(fmaf(w, acc[mt][nt][half2i*2+0], bsh[j0]));
                float v1 = tanha(fmaf(w, acc[mt][nt][half2i*2+1], bsh[j0+1]));
                if (grp == 0)      *(__half2*)&HPh[r*72+jj] = __floats2half2_rn(v0, v1);
                else if (grp == 1) *(__half2*)&HQh[r*72+jj] = __floats2half2_rn(v0, v1);
                else if (valid) {
                    atomicAdd(&FF[nl*64 + jj],     v0);
                    atomicAdd(&FF[nl*64 + jj + 1], v1);
                }
            }
        }
    }
    __syncthreads();
    if (tid < 128) {
        int nl = tid >> 6, c = tid & 63;
        outFF[(size_t)(n0 + nl) * 64 + c] = FF[tid] * (1.0f / 41.0f);
    }

    // ---- stage 2: (96x64)@(64x64) fp16 m16n8k16; W2 transposed in smem -----
    __half* W2Th = (__half*)Bbuf;              // 64 x 72 halfs = 2304 words
    const unsigned* W2Tw = (const unsigned*)W2Th;
    for (int p = 0; p < 2; p++) {
        const float* W2 = p ? Wq2 : Wp2;
        const float* b2 = p ? bq2 : bp2;
        const unsigned* Hw = (const unsigned*)(p ? HQh : HPh);
        float* outv = p ? g_neg : g_pos;
        __syncthreads();
        for (int t = tid; t < 4096; t += 256) {
            int kk = t >> 6, nn = t & 63;       // coalesced read W2[kk][nn]
            W2Th[nn * 72 + kk] = __float2half_rn(W2[t]);
        }
        if (tid < 64) bsh[tid] = b2[tid];
        __syncthreads();

        float acc2[3][2][4];
        #pragma unroll
        for (int mt = 0; mt < 3; mt++)
            #pragma unroll
            for (int nt = 0; nt < 2; nt++)
                #pragma unroll
                for (int q = 0; q < 4; q++) acc2[mt][nt][q] = 0.f;

        #pragma unroll
        for (int ks = 0; ks < 4; ks++) {        // K=64 in 4 steps of 16
            int kw = ks * 8 + tig;              // word offset along k
            unsigned a[3][4];
            #pragma unroll
            for (int mt = 0; mt < 3; mt++) {
                int R = wm * 48 + mt * 16;
                a[mt][0] = Hw[(R+gid  )*36 + kw];
                a[mt][1] = Hw[(R+gid+8)*36 + kw];
                a[mt][2] = Hw[(R+gid  )*36 + kw + 4];
                a[mt][3] = Hw[(R+gid+8)*36 + kw + 4];
            }
            #pragma unroll
            for (int nt = 0; nt < 2; nt++) {
                int Cb = wn * 16 + nt * 8;
                unsigned b0 = W2Tw[(Cb+gid)*36 + kw];
                unsigned b1 = W2Tw[(Cb+gid)*36 + kw + 4];
                #pragma unroll
                for (int mt = 0; mt < 3; mt++)
                    mma_f16(acc2[mt][nt], a[mt][0], a[mt][1], a[mt][2], a[mt][3], b0, b1);
            }
        }
        #pragma unroll
        for (int mt = 0; mt < 3; mt++)
            #pragma unroll
            for (int half2i = 0; half2i < 2; half2i++) {
                int r = wm * 48 + mt * 16 + gid + half2i * 8;
                bool valid = (r < 82);
                int nl = (r >= 41) ? 1 : 0;
                #pragma unroll
                for (int nt = 0; nt < 2; nt++) {
                    int j = wn * 16 + nt * 8 + tig * 2;
                    float v0 = tanha(acc2[mt][nt][half2i*2+0] + bsh[j]);
                    float v1 = tanha(acc2[mt][nt][half2i*2+1] + bsh[j+1]);
                    if (valid) {
                        atomicAdd(&PS[nl*64 + j],     v0);
                        atomicAdd(&PS[nl*64 + j + 1], v1);
                    }
                }
            }
        __syncthreads();
        if (tid < 128) {
            int nl = tid >> 6, c = tid & 63;
            outv[(size_t)(n0 + nl) * 64 + c] = PS[tid] * (1.0f / 41.0f);
            PS[tid] = 0.f;
        }
    }
    #undef STAGE_CHUNK
}

// ---------------- D0: scalar fp32 gram + sum + RAW minmax --------------------
__global__ void __launch_bounds__(256) k_d0(const float* __restrict__ sigma,
                                            float* __restrict__ outD)
{
    __shared__ float Ei[64][33], Ej[64][33];
    __shared__ float sred[256];
    __shared__ unsigned smn[256], smx[256];
    int i0 = blockIdx.y * 64, j0 = blockIdx.x * 64;
    int tid = threadIdx.x;
    for (int t = tid; t < 64 * 32; t += 256) {
        int r = t >> 5, c = t & 31;
        Ei[r][c] = g_emb[(i0 + r) * EMBD + c];
        Ej[r][c] = g_emb[(j0 + r) * EMBD + c];
    }
    __syncthreads();
    float inv = 1.0f / (2.0f * sigma[0] * sigma[0]);
    int tx = tid & 15, ty = tid >> 4;
    float acc[4][4];
    #pragma unroll
    for (int a = 0; a < 4; a++)
        #pragma unroll
        for (int b = 0; b < 4; b++) acc[a][b] = 0.0f;
    #pragma unroll 4
    for (int k = 0; k < 32; k++) {
        float av[4], bv[4];
        #pragma unroll
        for (int a = 0; a < 4; a++) av[a] = Ei[ty * 4 + a][k];
        #pragma unroll
        for (int b = 0; b < 4; b++) bv[b] = Ej[tx * 4 + b][k];
        #pragma unroll
        for (int a = 0; a < 4; a++)
            #pragma unroll
            for (int b = 0; b < 4; b++) acc[a][b] = fmaf(av[a], bv[b], acc[a][b]);
    }
    float lsum = 0.0f;
    unsigned mn = 0x7f800000u, mx = 0u;
    #pragma unroll
    for (int a = 0; a < 4; a++) {
        int i = i0 + ty * 4 + a;
        float si = g_sqn[i];
        #pragma unroll
        for (int b = 0; b < 4; b++) {
            int j = j0 + tx * 4 + b;
            float sqv = si + g_sqn[j] - 2.0f * acc[a][b];
            sqv = fmaxf(sqv, 0.0f);
            float d = (sqv > 0.0f) ? sqrta(sqv) : 0.0f;
            float e = __expf(-d * inv);
            if (i != j) {
                lsum += e;
                unsigned bb = __float_as_uint(e);
                mn = min(mn, bb); mx = max(mx, bb);
            }
            outD[(size_t)i * NN + (size_t)j] = e;
        }
    }
    sred[tid] = lsum; smn[tid] = mn; smx[tid] = mx;
    __syncthreads();
    for (int s2 = 128; s2 > 0; s2 >>= 1) {
        if (tid < s2) {
            sred[tid] += sred[tid + s2];
            smn[tid] = min(smn[tid], smn[tid + s2]);
            smx[tid] = max(smx[tid], smx[tid + s2]);
        }
        __syncthreads();
    }
    if (tid == 0) {
        atomicAdd(&g_dsum, (double)sred[0]);
        atomicMin(&g_minbits, smn[0]);
        atomicMax(&g_maxbits, smx[0]);
    }
}

__global__ void k_avg() {
    float avg = (float)(g_dsum / ((double)NN * (double)(NN - 1)));
    g_avg = avg;
    float mnr = __uint_as_float(g_minbits);
    float mxr = __uint_as_float(g_maxbits);
    float mn = (mnr < avg) ? 0.0f : mnr;
    float mx = mxr;
    if (mx == mn) mx = mn + 1.0f;
    g_mn = mn; g_invrange = 1.0f / (mx - mn);
}

__global__ void k_dfinal(float* __restrict__ outD)
{
    float avg = g_avg, mn = g_mn, inv = g_invrange;
    long long total = (long long)NN * NN;
    for (long long idx = (long long)blockIdx.x * blockDim.x + threadIdx.x; idx < total;
         idx += (long long)gridDim.x * blockDim.x) {
        int i = (int)(idx >> 12), j = (int)(idx & (NN - 1));
        float d = outD[idx];
        float t = (d < avg) ? 0.0f : d;
        float v = (t - mn) * inv;
        if (i == j) v = 1.0f;
        outD[idx] = v;
    }
}

__global__ void k_vecsqn()
{
    int n = blockIdx.x * blockDim.x + threadIdx.x;
    if (n >= NN) return;
    float a = 0.0f, b = 0.0f;
    #pragma unroll 8
    for (int o = 0; o < REDD; o++) {
        float p = g_pos[n * REDD + o]; a = fmaf(p, p, a);
        float q = g_neg[n * REDD + o]; b = fmaf(q, q, b);
    }
    g_psqn[n] = a; g_nsqn[n] = b;
}

// ========== k_simmma: 128x128 tiles of exp(-cdist) sums via tf32 mma ========
#define SIM_SMEM_BYTES (2 * 128 * 68 * 4)
__global__ void __launch_bounds__(256) k_simmma()
{
    extern __shared__ unsigned simsm[];
    unsigned* Xsm = simsm;
    unsigned* Ysm = simsm + 128 * 68;
    __shared__ float xq[128], yq[128];
    __shared__ float sred[256];
    int tid = threadIdx.x;
    int zi = blockIdx.z;
    int i0 = blockIdx.y * 128, j0 = blockIdx.x * 128;
    const float* Ys  = zi ? g_neg  : g_pos;
    const float* Ysq = zi ? g_nsqn : g_psqn;
    for (int t = tid; t < 128 * 16; t += 256) {
        int r = t >> 4, c4 = (t & 15) * 4;
        float4 v = *(const float4*)&g_pos[(size_t)(i0 + r) * REDD + c4];
        Xsm[r*68+c4+0] = f2tf32(v.x); Xsm[r*68+c4+1] = f2tf32(v.y);
        Xsm[r*68+c4+2] = f2tf32(v.z); Xsm[r*68+c4+3] = f2tf32(v.w);
        float4 w = *(const float4*)&Ys[(size_t)(j0 + r) * REDD + c4];
        Ysm[r*68+c4+0] = f2tf32(w.x); Ysm[r*68+c4+1] = f2tf32(w.y);
        Ysm[r*68+c4+2] = f2tf32(w.z); Ysm[r*68+c4+3] = f2tf32(w.w);
    }
    if (tid < 128) { xq[tid] = g_psqn[i0 + tid]; yq[tid] = Ysq[j0 + tid]; }
    __syncthreads();

    int warp = tid >> 5, lane = tid & 31, gid = lane >> 2, tig = lane & 3;
    int wm = warp >> 2, wn = warp & 3;
    float acc[4][4][4];
    #pragma unroll
    for (int mt = 0; mt < 4; mt++)
        #pragma unroll
        for (int nt = 0; nt < 4; nt++)
            #pragma unroll
            for (int q = 0; q < 4; q++) acc[mt][nt][q] = 0.f;

    #pragma unroll
    for (int ks = 0; ks < 8; ks++) {
        int kb = ks * 8;
        unsigned a[4][4];
        #pragma unroll
        for (int mt = 0; mt < 4; mt++) {
            int R = wm * 64 + mt * 16;
            a[mt][0] = Xsm[(R+gid  )*68 + kb+tig];
            a[mt][1] = Xsm[(R+gid+8)*68 + kb+tig];
            a[mt][2] = Xsm[(R+gid  )*68 + kb+tig+4];
            a[mt][3] = Xsm[(R+gid+8)*68 + kb+tig+4];
        }
        #pragma unroll
        for (int nt = 0; nt < 4; nt++) {
            int Cb = wn * 32 + nt * 8;
            unsigned b0 = Ysm[(Cb+gid)*68 + kb+tig];
            unsigned b1 = Ysm[(Cb+gid)*68 + kb+tig+4];
            #pragma unroll
            for (int mt = 0; mt < 4; mt++)
                mma_tf32(acc[mt][nt], a[mt][0], a[mt][1], a[mt][2], a[mt][3], b0, b1);
        }
    }
    float lsum = 0.f;
    #pragma unroll
    for (int mt = 0; mt < 4; mt++)
        #pragma unroll
        for (int nt = 0; nt < 4; nt++)
            #pragma unroll
            for (int q = 0; q < 4; q++) {
                int il = wm*64 + mt*16 + gid + ((q >> 1) << 3);
                int jl = wn*32 + nt*8  + tig*2 + (q & 1);
                float sq = xq[il] + yq[jl] - 2.0f * acc[mt][nt][q];
                sq = fmaxf(sq, 0.f);
                float d = (sq > 0.f) ? sqrta(sq) : 0.f;
                lsum += __expf(-d);
            }
    sred[tid] = lsum;
    __syncthreads();
    for (int s2 = 128; s2 > 0; s2 >>= 1) {
        if (tid < s2) sred[tid] += sred[tid + s2];
        __syncthreads();
    }
    if (tid == 0) atomicAdd(zi ? &g_nsim : &g_psim, (double)sred[0]);
}

__global__ void k_loss(float* __restrict__ o)
{
    o[0] = (float)(log(g_nsim) - log(g_psim));
}

// ----------------------------- launcher --------------------------------------
extern "C" void kernel_launch(void* const* d_in, const int* in_sizes, int n_in,
                              void* d_out, int out_size)
{
    const float* A     = (const float*)d_in[0];
    const int*   C     = (const int*)  d_in[1];
    const float* L     = (const float*)d_in[2];
    const float* W1    = (const float*)d_in[3];
    const float* b1    = (const float*)d_in[4];
    const float* gamma = (const float*)d_in[5];
    const float* beta  = (const float*)d_in[6];
    const float* sigma = (const float*)d_in[7];
    const float* Pw    = (const float*)d_in[8];
    const float* Nw    = (const float*)d_in[9];
    const float* Wp1   = (const float*)d_in[10];
    const float* bp1   = (const float*)d_in[11];
    const float* Wp2   = (const float*)d_in[12];
    const float* bp2   = (const float*)d_in[13];
    const float* Wq1   = (const float*)d_in[14];
    const float* bq1   = (const float*)d_in[15];
    const float* Wq2   = (const float*)d_in[16];
    const float* bq2   = (const float*)d_in[17];
    const float* Wa    = (const float*)d_in[18];
    const float* ba    = (const float*)d_in[19];

    float* out   = (float*)d_out;
    float* outFF = out;                 // [4096*64]
    float* outL  = out + NN * REDD;     // [1]
    float* outD  = out + NN * REDD + 1; // [4096*4096], only 4B-aligned

    cudaFuncSetAttribute(k_fused, cudaFuncAttributeMaxDynamicSharedMemorySize, FUSED_SMEM_BYTES);
    cudaFuncSetAttribute(k_simmma, cudaFuncAttributeMaxDynamicSharedMemorySize, SIM_SMEM_BYTES);

    // k_fused at launch #4: the ncu window lands on launch #4.
    k_reset<<<1, 1>>>();
    k_interp<<<NN / 8, 256>>>(A, C, W1, b1);
    k_bnstats<<<64, 256>>>();
    k_fused<<<NN / 2, 256, FUSED_SMEM_BYTES>>>(L, C, Pw, Nw,
                                               Wp1, bp1, Wq1, bq1, Wa, ba,
                                               Wp2, bp2, Wq2, bq2, outFF);
    k_bnfin<<<1, 32>>>(gamma, beta);
    k_emb<<<NN / 8, 256>>>();
    k_d0<<<dim3(64, 64), 256>>>(sigma, outD);
    k_avg<<<1, 1>>>();
    k_dfinal<<<4096, 256>>>(outD);
    k_vecsqn<<<16, 256>>>();
    k_simmma<<<dim3(32, 32, 2), 256, SIM_SMEM_BYTES>>>();
    k_loss<<<1, 1>>>(outL);
}